// round 7
// baseline (speedup 1.0000x reference)
#include <cuda_runtime.h>
#include <cuda_bf16.h>
#include <math.h>
#include <stdint.h>

#define SEQ 1024
#define HID 4096
#define NH  64
#define HD  64
#define SZ  (SEQ*HID)
#define SZW (HID*HID)

__device__ float          g_kvrg[4*SZ];     // k,v,r,g(silu) fp32
__device__ float          g_opart[8*SZ];    // WKV partials per d-group
__device__ __nv_bfloat16  g_mAh[4*SZ];      // mixed activations hi
__device__ __nv_bfloat16  g_mAl[4*SZ];      // mixed activations lo
__device__ __nv_bfloat16  g_abh[SZ];        // normed/gated hi
__device__ __nv_bfloat16  g_abl[SZ];        // normed/gated lo
__device__ __nv_bfloat16  g_Wh[5*SZW];      // weights hi (k,v,r,g,o)
__device__ __nv_bfloat16  g_Wl[5*SZW];      // weights lo

__device__ __forceinline__ uint32_t pk(__nv_bfloat16 a, __nv_bfloat16 b){
    __nv_bfloat162 t = __halves2bfloat162(a, b);
    return *reinterpret_cast<uint32_t*>(&t);
}
__device__ __forceinline__ void split_bf(float x, __nv_bfloat16& h, __nv_bfloat16& l){
    h = __float2bfloat16(x);
    l = __float2bfloat16(x - __bfloat162float(h));
}
__device__ __forceinline__ float silu(float x){ return x / (1.f + expf(-x)); }
__device__ __forceinline__ uint32_t smem_u32(const void* p){
    uint32_t a;
    asm("{ .reg .u64 t; cvta.to.shared.u64 t, %1; cvt.u32.u64 %0, t; }" : "=r"(a) : "l"(p));
    return a;
}
__device__ __forceinline__ void mma16816(float* c, const uint32_t* a, uint32_t b0, uint32_t b1){
    asm volatile("mma.sync.aligned.m16n8k16.row.col.f32.bf16.bf16.f32 "
        "{%0,%1,%2,%3}, {%4,%5,%6,%7}, {%8,%9}, {%0,%1,%2,%3};"
        : "+f"(c[0]), "+f"(c[1]), "+f"(c[2]), "+f"(c[3])
        : "r"(a[0]), "r"(a[1]), "r"(a[2]), "r"(a[3]), "r"(b0), "r"(b1));
}
__device__ __forceinline__ void ldsm4(uint32_t* r, uint32_t a){
    asm volatile("ldmatrix.sync.aligned.m8n8.x4.shared.b16 {%0,%1,%2,%3}, [%4];"
        : "=r"(r[0]), "=r"(r[1]), "=r"(r[2]), "=r"(r[3]) : "r"(a));
}
__device__ __forceinline__ void cpa16(uint32_t dst, const void* src){
    asm volatile("cp.async.cg.shared.global [%0], [%1], 16;" :: "r"(dst), "l"(src));
}
#define CPA_COMMIT() asm volatile("cp.async.commit_group;" ::: "memory")
#define CPA_WAIT1()  asm volatile("cp.async.wait_group 1;" ::: "memory")

// ---------------- weight prepass: fp32 -> split bf16 ------------------------
__global__ __launch_bounds__(256) void prepass_w_kernel(
    const float* __restrict__ wk, const float* __restrict__ wv,
    const float* __restrict__ wr, const float* __restrict__ wg,
    const float* __restrict__ wo)
{
    const int p = blockIdx.y;
    const float* W = (p==0)?wk:(p==1)?wv:(p==2)?wr:(p==3)?wg:wo;
    size_t idx = ((size_t)blockIdx.x*256 + threadIdx.x)*4;
    float4 w4 = *(const float4*)(W + idx);
    __nv_bfloat16 h0,h1,h2,h3,l0,l1,l2,l3;
    split_bf(w4.x,h0,l0); split_bf(w4.y,h1,l1); split_bf(w4.z,h2,l2); split_bf(w4.w,h3,l3);
    *(uint2*)(g_Wh + (size_t)p*SZW + idx) = make_uint2(pk(h0,h1), pk(h2,h3));
    *(uint2*)(g_Wl + (size_t)p*SZW + idx) = make_uint2(pk(l0,l1), pk(l2,l3));
}

// ---------------- activation prepass: mix -> split bf16 ---------------------
__global__ __launch_bounds__(256) void prepass_kernel(
    const float* __restrict__ hidden, const float* __restrict__ mk,
    const float* __restrict__ mv, const float* __restrict__ mr, const float* __restrict__ mg)
{
    int idx = (blockIdx.x*256 + threadIdx.x)*4;
    int t = idx >> 12, c = idx & 4095;
    float4 hv = *(const float4*)(hidden + idx);
    float4 sv = make_float4(0.f,0.f,0.f,0.f);
    if (t > 0) sv = *(const float4*)(hidden + idx - HID);
    const float* ms[4] = {mk, mv, mr, mg};
    #pragma unroll
    for (int p = 0; p < 4; p++){
        float4 m = *(const float4*)(ms[p] + c);
        float x0 = hv.x*m.x + sv.x*(1.f-m.x), x1 = hv.y*m.y + sv.y*(1.f-m.y);
        float x2 = hv.z*m.z + sv.z*(1.f-m.z), x3 = hv.w*m.w + sv.w*(1.f-m.w);
        __nv_bfloat16 h0,h1,h2,h3,l0,l1,l2,l3;
        split_bf(x0,h0,l0); split_bf(x1,h1,l1); split_bf(x2,h2,l2); split_bf(x3,h3,l3);
        *(uint2*)(g_mAh + (size_t)p*SZ + idx) = make_uint2(pk(h0,h1), pk(h2,h3));
        *(uint2*)(g_mAl + (size_t)p*SZ + idx) = make_uint2(pk(l0,l1), pk(l2,l3));
    }
}

// ---------------- mma.sync GEMM, 3-stage cp.async pipeline ------------------
// C[M,N] = A[M,K] * W[N,K]^T.  Tile 128x128, KC=64, 8 warps (4m x 2n).
// Split-bf16: C = Ah*Bh + Ah*Bl + Al*Bh
#define KC 64
#define SP 72
#define TH (128*SP)              // elems per tile-half
#define NSTAGE 3
#define GSMEM (NSTAGE*4*TH*2)    // bytes

__global__ __launch_bounds__(256) void gemm_kernel(int mode, float* __restrict__ dout)
{
    extern __shared__ __nv_bfloat16 sm[];
    const int tid = threadIdx.x, z = blockIdx.z;
    const __nv_bfloat16 *AhG, *AlG, *BhG, *BlG;
    float* outp;
    bool do_silu = false;
    if (mode == 0){
        AhG = g_mAh + (size_t)z*SZ; AlG = g_mAl + (size_t)z*SZ;
        BhG = g_Wh + (size_t)z*SZW; BlG = g_Wl + (size_t)z*SZW;
        outp = g_kvrg + (size_t)z*SZ; do_silu = (z==3);
    } else {
        AhG = g_abh; AlG = g_abl;
        BhG = g_Wh + 4*(size_t)SZW; BlG = g_Wl + 4*(size_t)SZW;
        outp = dout;
    }

    const int m0 = blockIdx.x*128, n0 = blockIdx.y*128;
    const int wid = tid>>5, lane = tid&31;
    const int wm = (wid&3)*32, wn = (wid>>2)*64;
    const int r = lane>>2, q = lane&3;
    const uint32_t sbase = smem_u32(sm);

    const int crow = tid>>3, cseg = tid&7;          // copy: 32 rows x 8 segs / 256 thr
    const size_t gAoff = (size_t)(m0+crow)*HID + cseg*8;
    const size_t gBoff = (size_t)(n0+crow)*HID + cseg*8;
    const uint32_t soff = (uint32_t)(crow*SP + cseg*8)*2;

    float acc[2][8][4];
    #pragma unroll
    for (int i=0;i<2;i++)
        #pragma unroll
        for (int j=0;j<8;j++)
            #pragma unroll
            for (int k=0;k<4;k++) acc[i][j][k]=0.f;

    auto issue = [&](int c, int s){
        const int k0 = c*KC;
        const uint32_t st = sbase + (uint32_t)(s*4*TH)*2;
        #pragma unroll
        for (int i = 0; i < 4; i++){
            const uint32_t dof = soff + (uint32_t)(i*32*SP)*2;
            const size_t ga = gAoff + k0 + (size_t)i*32*HID;
            const size_t gb = gBoff + k0 + (size_t)i*32*HID;
            cpa16(st + dof,                    AhG + ga);
            cpa16(st + (uint32_t)TH*2   + dof, AlG + ga);
            cpa16(st + (uint32_t)2*TH*2 + dof, BhG + gb);
            cpa16(st + (uint32_t)3*TH*2 + dof, BlG + gb);
        }
    };

    issue(0, 0); CPA_COMMIT();
    issue(1, 1); CPA_COMMIT();

    const int NCH = HID/KC;
    for (int c = 0; c < NCH; c++){
        const int s = c % NSTAGE;
        CPA_WAIT1();
        __syncthreads();
        if (c + 2 < NCH) issue(c + 2, (c + 2) % NSTAGE);
        CPA_COMMIT();

        const uint32_t stA_h = sbase + (uint32_t)(s*4*TH)*2;
        const uint32_t stA_l = stA_h + (uint32_t)TH*2;
        const uint32_t stB_h = stA_h + (uint32_t)2*TH*2;
        const uint32_t stB_l = stA_h + (uint32_t)3*TH*2;

        #pragma unroll
        for (int ko = 0; ko < KC; ko += 16){
            uint32_t ah[2][4], al[2][4], bh[8][2], bl[8][2];
            // A frags: ldsm4, lanes 0-15 rows (k lo), 16-31 same rows (k hi)
            const int arow = wm + (lane&15), acol = ko + (lane>>4)*8;
            #pragma unroll
            for (int fm = 0; fm < 2; fm++){
                const uint32_t ao = (uint32_t)((arow + fm*16)*SP + acol)*2;
                ldsm4(ah[fm], stA_h + ao);
                ldsm4(al[fm], stA_l + ao);
            }
            // B frags: ldsm4 over 32 consecutive n-rows (4 fn frags / op)
            #pragma unroll
            for (int fnb = 0; fnb < 2; fnb++){
                const int brow = wn + fnb*32 + lane;
                #pragma unroll
                for (int kh = 0; kh < 2; kh++){
                    const uint32_t bo = (uint32_t)(brow*SP + ko + kh*8)*2;
                    uint32_t th[4], tl[4];
                    ldsm4(th, stB_h + bo);
                    ldsm4(tl, stB_l + bo);
                    #pragma unroll
                    for (int j = 0; j < 4; j++){
                        bh[fnb*4+j][kh] = th[j];
                        bl[fnb*4+j][kh] = tl[j];
                    }
                }
            }
            // term-outermost: 16 independent accs between acc reuse
            #pragma unroll
            for (int fn = 0; fn < 8; fn++)
                #pragma unroll
                for (int fm = 0; fm < 2; fm++)
                    mma16816(acc[fm][fn], ah[fm], bh[fn][0], bh[fn][1]);
            #pragma unroll
            for (int fn = 0; fn < 8; fn++)
                #pragma unroll
                for (int fm = 0; fm < 2; fm++)
                    mma16816(acc[fm][fn], ah[fm], bl[fn][0], bl[fn][1]);
            #pragma unroll
            for (int fn = 0; fn < 8; fn++)
                #pragma unroll
                for (int fm = 0; fm < 2; fm++)
                    mma16816(acc[fm][fn], al[fm], bh[fn][0], bh[fn][1]);
        }
        __syncthreads();
    }

    #pragma unroll
    for (int fm = 0; fm < 2; fm++){
        #pragma unroll
        for (int fn = 0; fn < 8; fn++){
            int row0 = m0 + wm + fm*16 + r;
            int col  = n0 + wn + fn*8 + q*2;
            float2 v0 = make_float2(acc[fm][fn][0], acc[fm][fn][1]);
            float2 v1 = make_float2(acc[fm][fn][2], acc[fm][fn][3]);
            if (do_silu){
                v0.x = silu(v0.x); v0.y = silu(v0.y);
                v1.x = silu(v1.x); v1.y = silu(v1.y);
            }
            *(float2*)(outp + (size_t)row0*HID + col)     = v0;
            *(float2*)(outp + (size_t)(row0+8)*HID + col) = v1;
        }
    }
}

// ---------------- WKV recurrence, barrier-light -----------------------------
__global__ __launch_bounds__(256) void wkv_kernel(
    const float* __restrict__ time_decay, const float* __restrict__ time_faaaa)
{
    const int head = blockIdx.x, ehalf = blockIdx.y;
    const int tid = threadIdx.x, eg = tid & 31, dg = tid >> 5;
    __shared__ float ks[16][64], rs[16][64], vs[16][32];

    float td[8], tf[8], stv[8];
    #pragma unroll
    for (int j = 0; j < 8; j++){
        int d = dg*8 + j;
        td[j] = expf(-expf(time_decay[head*HD + d]));
        tf[j] = time_faaaa[head*HD + d];
        stv[j] = 0.f;
    }
    const float* kb = g_kvrg + 0*(size_t)SZ + head*HD;
    const float* vb = g_kvrg + 1*(size_t)SZ + head*HD + ehalf*32;
    const float* rb = g_kvrg + 2*(size_t)SZ + head*HD;
    float* op = g_opart + (size_t)dg*SZ + head*HD + ehalf*32;

    const int ktrow = tid >> 4, kseg = tid & 15;
    const int vtrow = tid >> 3, vseg = tid & 7;
    float4 ka, ra, va;
    ka = *(const float4*)(kb + (size_t)ktrow*HID + kseg*4);
    ra = *(const float4*)(rb + (size_t)ktrow*HID + kseg*4);
    if (tid < 128) va = *(const float4*)(vb + (size_t)vtrow*HID + vseg*4);

    for (int c = 0; c < SEQ/16; c++){
        __syncthreads();
        *(float4*)&ks[ktrow][kseg*4] = ka;
        *(float4*)&rs[ktrow][kseg*4] = ra;
        if (tid < 128) *(float4*)&vs[vtrow][vseg*4] = va;
        __syncthreads();
        if (c < SEQ/16 - 1){
            const size_t t1 = (size_t)(c+1)*16;
            ka = *(const float4*)(kb + (t1+ktrow)*HID + kseg*4);
            ra = *(const float4*)(rb + (t1+ktrow)*HID + kseg*4);
            if (tid < 128) va = *(const float4*)(vb + (t1+vtrow)*HID + vseg*4);
        }
        #pragma unroll
        for (int tt = 0; tt < 16; tt++){
            const float ve = vs[tt][eg];
            float4 k0 = *(const float4*)&ks[tt][dg*8];
            float4 k1 = *(const float4*)&ks[tt][dg*8+4];
            float4 r0 = *(const float4*)&rs[tt][dg*8];
            float4 r1 = *(const float4*)&rs[tt][dg*8+4];
            float kv, o = 0.f;
            kv = k0.x*ve; o = fmaf(r0.x, fmaf(tf[0],kv,stv[0]), o); stv[0] = fmaf(td[0],stv[0],kv);
            kv = k0.y*ve; o = fmaf(r0.y, fmaf(tf[1],kv,stv[1]), o); stv[1] = fmaf(td[1],stv[1],kv);
            kv = k0.z*ve; o = fmaf(r0.z, fmaf(tf[2],kv,stv[2]), o); stv[2] = fmaf(td[2],stv[2],kv);
            kv = k0.w*ve; o = fmaf(r0.w, fmaf(tf[3],kv,stv[3]), o); stv[3] = fmaf(td[3],stv[3],kv);
            kv = k1.x*ve; o = fmaf(r1.x, fmaf(tf[4],kv,stv[4]), o); stv[4] = fmaf(td[4],stv[4],kv);
            kv = k1.y*ve; o = fmaf(r1.y, fmaf(tf[5],kv,stv[5]), o); stv[5] = fmaf(td[5],stv[5],kv);
            kv = k1.z*ve; o = fmaf(r1.z, fmaf(tf[6],kv,stv[6]), o); stv[6] = fmaf(td[6],stv[6],kv);
            kv = k1.w*ve; o = fmaf(r1.w, fmaf(tf[7],kv,stv[7]), o); stv[7] = fmaf(td[7],stv[7],kv);
            op[(size_t)(c*16+tt)*HID + eg] = o;
        }
    }
}

// ---------------- GroupNorm + gate + split-bf16 -----------------------------
__global__ __launch_bounds__(256) void norm_kernel(
    const float* __restrict__ gnw, const float* __restrict__ gnb)
{
    const int wid = threadIdx.x >> 5, lane = threadIdx.x & 31;
    const int g = blockIdx.x*8 + wid;
    const int t = g >> 6, h = g & 63, e0 = lane*2;
    const size_t bse = (size_t)t*HID + h*HD + e0;

    float o0 = 0.f, o1 = 0.f;
    #pragma unroll
    for (int dg = 0; dg < 8; dg++){
        float2 v = *(const float2*)(g_opart + (size_t)dg*SZ + bse);
        o0 += v.x; o1 += v.y;
    }
    float s = o0 + o1, s2 = o0*o0 + o1*o1;
    #pragma unroll
    for (int off = 16; off > 0; off >>= 1){
        s  += __shfl_xor_sync(0xffffffffu, s,  off);
        s2 += __shfl_xor_sync(0xffffffffu, s2, off);
    }
    const float mean = s * (1.f/64.f);
    const float var  = s2 * (1.f/64.f) - mean*mean;
    const float rstd = rsqrtf(var + 1e-5f);
    float2 gt = *(const float2*)(g_kvrg + 3*(size_t)SZ + bse);
    const float w0 = gnw[h*HD+e0], w1 = gnw[h*HD+e0+1];
    const float b0 = gnb[h*HD+e0], b1 = gnb[h*HD+e0+1];
    float y0 = ((o0-mean)*rstd*w0 + b0) * gt.x;
    float y1 = ((o1-mean)*rstd*w1 + b1) * gt.y;
    __nv_bfloat16 h0,h1,l0,l1;
    split_bf(y0,h0,l0); split_bf(y1,h1,l1);
    *(uint32_t*)(g_abh + bse) = pk(h0,h1);
    *(uint32_t*)(g_abl + bse) = pk(l0,l1);
}

// ---------------------------------------------------------------------------
extern "C" void kernel_launch(void* const* d_in, const int* in_sizes, int n_in,
                              void* d_out, int out_size)
{
    const float* hidden     = (const float*)d_in[0];
    const float* w_key      = (const float*)d_in[1];
    const float* w_value    = (const float*)d_in[2];
    const float* w_recept   = (const float*)d_in[3];
    const float* w_gate     = (const float*)d_in[4];
    const float* w_output   = (const float*)d_in[5];
    const float* tm_key     = (const float*)d_in[6];
    const float* tm_value   = (const float*)d_in[7];
    const float* tm_recept  = (const float*)d_in[8];
    const float* tm_gate    = (const float*)d_in[9];
    const float* time_decay = (const float*)d_in[10];
    const float* time_faaaa = (const float*)d_in[11];
    const float* gn_w       = (const float*)d_in[12];
    const float* gn_b       = (const float*)d_in[13];

    cudaFuncSetAttribute(gemm_kernel, cudaFuncAttributeMaxDynamicSharedMemorySize, GSMEM);

    dim3 gw(SZW/1024, 5);
    prepass_w_kernel<<<gw, 256>>>(w_key, w_value, w_recept, w_gate, w_output);
    prepass_kernel<<<SZ/1024, 256>>>(hidden, tm_key, tm_value, tm_recept, tm_gate);

    dim3 gproj(SEQ/128, HID/128, 4);
    gemm_kernel<<<gproj, 256, GSMEM>>>(0, nullptr);

    dim3 gwkv(NH, 2);
    wkv_kernel<<<gwkv, 256>>>(time_decay, time_faaaa);

    norm_kernel<<<SEQ*NH/8, 256>>>(gn_w, gn_b);

    dim3 gout(SEQ/128, HID/128, 1);
    gemm_kernel<<<gout, 256, GSMEM>>>(1, (float*)d_out);
}

// round 8
// speedup vs baseline: 1.4917x; 1.4917x over previous
#include <cuda_runtime.h>
#include <cuda_fp16.h>
#include <math.h>
#include <stdint.h>

#define SEQ 1024
#define HID 4096
#define NH  64
#define HD  64
#define SZ  (SEQ*HID)
#define SZW (HID*HID)

__device__ float   g_kvrg[4*SZ];     // k,v,r,g(silu) fp32
__device__ float   g_opart[8*SZ];    // WKV partials per d-group
__device__ __half  g_mAh[4*SZ];      // mixed activations hi (fp16)
__device__ __half  g_mAl[4*SZ];      // mixed activations lo (fp16)
__device__ __half  g_abh[SZ];        // normed/gated hi
__device__ __half  g_abl[SZ];        // normed/gated lo
__device__ __half  g_W[5*SZW];       // weights fp16 (k,v,r,g,o)

__device__ __forceinline__ uint32_t pkh(__half a, __half b){
    __half2 t = __halves2half2(a, b);
    return *reinterpret_cast<uint32_t*>(&t);
}
__device__ __forceinline__ void split_h(float x, __half& h, __half& l){
    h = __float2half(x);
    l = __float2half(x - __half2float(h));
}
__device__ __forceinline__ float silu(float x){ return x / (1.f + expf(-x)); }
__device__ __forceinline__ uint32_t smem_u32(const void* p){
    uint32_t a;
    asm("{ .reg .u64 t; cvta.to.shared.u64 t, %1; cvt.u32.u64 %0, t; }" : "=r"(a) : "l"(p));
    return a;
}
__device__ __forceinline__ void mma16816(float* c, const uint32_t* a, uint32_t b0, uint32_t b1){
    asm volatile("mma.sync.aligned.m16n8k16.row.col.f32.f16.f16.f32 "
        "{%0,%1,%2,%3}, {%4,%5,%6,%7}, {%8,%9}, {%0,%1,%2,%3};"
        : "+f"(c[0]), "+f"(c[1]), "+f"(c[2]), "+f"(c[3])
        : "r"(a[0]), "r"(a[1]), "r"(a[2]), "r"(a[3]), "r"(b0), "r"(b1));
}
__device__ __forceinline__ void ldsm4(uint32_t* r, uint32_t a){
    asm volatile("ldmatrix.sync.aligned.m8n8.x4.shared.b16 {%0,%1,%2,%3}, [%4];"
        : "=r"(r[0]), "=r"(r[1]), "=r"(r[2]), "=r"(r[3]) : "r"(a));
}
__device__ __forceinline__ void ldsm2(uint32_t* r, uint32_t a){
    asm volatile("ldmatrix.sync.aligned.m8n8.x2.shared.b16 {%0,%1}, [%2];"
        : "=r"(r[0]), "=r"(r[1]) : "r"(a));
}
__device__ __forceinline__ void cpa16(uint32_t dst, const void* src){
    asm volatile("cp.async.cg.shared.global [%0], [%1], 16;" :: "r"(dst), "l"(src));
}
#define CPA_COMMIT() asm volatile("cp.async.commit_group;" ::: "memory")
#define CPA_WAIT1()  asm volatile("cp.async.wait_group 1;" ::: "memory")

// ---------------- weight prepass: fp32 -> fp16 ------------------------------
__global__ __launch_bounds__(256) void prepass_w_kernel(
    const float* __restrict__ wk, const float* __restrict__ wv,
    const float* __restrict__ wr, const float* __restrict__ wg,
    const float* __restrict__ wo)
{
    const int p = blockIdx.y;
    const float* W = (p==0)?wk:(p==1)?wv:(p==2)?wr:(p==3)?wg:wo;
    size_t idx = ((size_t)blockIdx.x*256 + threadIdx.x)*4;
    float4 w4 = *(const float4*)(W + idx);
    *(uint2*)(g_W + (size_t)p*SZW + idx) =
        make_uint2(pkh(__float2half(w4.x), __float2half(w4.y)),
                   pkh(__float2half(w4.z), __float2half(w4.w)));
}

// ---------------- activation prepass: mix -> split fp16 ---------------------
__global__ __launch_bounds__(256) void prepass_kernel(
    const float* __restrict__ hidden, const float* __restrict__ mk,
    const float* __restrict__ mv, const float* __restrict__ mr, const float* __restrict__ mg)
{
    int idx = (blockIdx.x*256 + threadIdx.x)*4;
    int t = idx >> 12, c = idx & 4095;
    float4 hv = *(const float4*)(hidden + idx);
    float4 sv = make_float4(0.f,0.f,0.f,0.f);
    if (t > 0) sv = *(const float4*)(hidden + idx - HID);
    const float* ms[4] = {mk, mv, mr, mg};
    #pragma unroll
    for (int p = 0; p < 4; p++){
        float4 m = *(const float4*)(ms[p] + c);
        float x0 = hv.x*m.x + sv.x*(1.f-m.x), x1 = hv.y*m.y + sv.y*(1.f-m.y);
        float x2 = hv.z*m.z + sv.z*(1.f-m.z), x3 = hv.w*m.w + sv.w*(1.f-m.w);
        __half h0,h1,h2,h3,l0,l1,l2,l3;
        split_h(x0,h0,l0); split_h(x1,h1,l1); split_h(x2,h2,l2); split_h(x3,h3,l3);
        *(uint2*)(g_mAh + (size_t)p*SZ + idx) = make_uint2(pkh(h0,h1), pkh(h2,h3));
        *(uint2*)(g_mAl + (size_t)p*SZ + idx) = make_uint2(pkh(l0,l1), pkh(l2,l3));
    }
}

// ---------------- mma.sync GEMM, 3-stage cp.async pipeline ------------------
// C[M,N] = A[M,K] * W[N,K]^T.  Tile 128x128, KC=64, 8 warps (4m x 2n).
// fp16 2-term: C = Ah*B + Al*B  (A split fp16; B single fp16)
#define KC 64
#define SP 72
#define TH (128*SP)              // elems per tile-half
#define NSTAGE 3
#define GSMEM (NSTAGE*3*TH*2)    // bytes: Ah | Al | B per stage

__global__ __launch_bounds__(256) void gemm_kernel(int mode, float* __restrict__ dout)
{
    extern __shared__ __half sm[];
    const int tid = threadIdx.x, z = blockIdx.z;
    const __half *AhG, *AlG, *BG;
    float* outp;
    bool do_silu = false;
    if (mode == 0){
        AhG = g_mAh + (size_t)z*SZ; AlG = g_mAl + (size_t)z*SZ;
        BG  = g_W + (size_t)z*SZW;
        outp = g_kvrg + (size_t)z*SZ; do_silu = (z==3);
    } else {
        AhG = g_abh; AlG = g_abl;
        BG  = g_W + 4*(size_t)SZW;
        outp = dout;
    }

    const int m0 = blockIdx.x*128, n0 = blockIdx.y*128;
    const int wid = tid>>5, lane = tid&31;
    const int wm = (wid&3)*32, wn = (wid>>2)*64;
    const int r = lane>>2, q = lane&3;
    const uint32_t sbase = smem_u32(sm);

    const int crow = tid>>3, cseg = tid&7;          // copy: 32 rows x 8 segs / 256 thr
    const size_t gAoff = (size_t)(m0+crow)*HID + cseg*8;
    const size_t gBoff = (size_t)(n0+crow)*HID + cseg*8;
    const uint32_t soff = (uint32_t)(crow*SP + cseg*8)*2;

    float acc[2][8][4];
    #pragma unroll
    for (int i=0;i<2;i++)
        #pragma unroll
        for (int j=0;j<8;j++)
            #pragma unroll
            for (int k=0;k<4;k++) acc[i][j][k]=0.f;

    auto issue = [&](int c, int s){
        const int k0 = c*KC;
        const uint32_t st = sbase + (uint32_t)(s*3*TH)*2;
        #pragma unroll
        for (int i = 0; i < 4; i++){
            const uint32_t dof = soff + (uint32_t)(i*32*SP)*2;
            const size_t ga = gAoff + k0 + (size_t)i*32*HID;
            const size_t gb = gBoff + k0 + (size_t)i*32*HID;
            cpa16(st + dof,                    AhG + ga);
            cpa16(st + (uint32_t)TH*2   + dof, AlG + ga);
            cpa16(st + (uint32_t)2*TH*2 + dof, BG  + gb);
        }
    };

    issue(0, 0); CPA_COMMIT();
    issue(1, 1); CPA_COMMIT();

    const int NCH = HID/KC;
    for (int c = 0; c < NCH; c++){
        const int s = c % NSTAGE;
        CPA_WAIT1();
        __syncthreads();
        if (c + 2 < NCH) issue(c + 2, (c + 2) % NSTAGE);
        CPA_COMMIT();

        const uint32_t stA_h = sbase + (uint32_t)(s*3*TH)*2;
        const uint32_t stA_l = stA_h + (uint32_t)TH*2;
        const uint32_t stB   = stA_h + (uint32_t)2*TH*2;

        #pragma unroll
        for (int ko = 0; ko < KC; ko += 16){
            uint32_t ah[2][4], al[2][4], bb[8][2];
            const int arow = wm + (lane&15), acol = ko + (lane>>4)*8;
            #pragma unroll
            for (int fm = 0; fm < 2; fm++){
                const uint32_t ao = (uint32_t)((arow + fm*16)*SP + acol)*2;
                ldsm4(ah[fm], stA_h + ao);
                ldsm4(al[fm], stA_l + ao);
            }
            const int brow = wn + (lane&7), bcol = ko + ((lane>>3)&1)*8;
            #pragma unroll
            for (int fn = 0; fn < 8; fn++){
                const uint32_t bo = (uint32_t)((brow + fn*8)*SP + bcol)*2;
                ldsm2(bb[fn], stB + bo);
            }
            #pragma unroll
            for (int fn = 0; fn < 8; fn++)
                #pragma unroll
                for (int fm = 0; fm < 2; fm++){
                    mma16816(acc[fm][fn], ah[fm], bb[fn][0], bb[fn][1]);
                    mma16816(acc[fm][fn], al[fm], bb[fn][0], bb[fn][1]);
                }
        }
        __syncthreads();
    }

    #pragma unroll
    for (int fm = 0; fm < 2; fm++){
        #pragma unroll
        for (int fn = 0; fn < 8; fn++){
            int row0 = m0 + wm + fm*16 + r;
            int col  = n0 + wn + fn*8 + q*2;
            float2 v0 = make_float2(acc[fm][fn][0], acc[fm][fn][1]);
            float2 v1 = make_float2(acc[fm][fn][2], acc[fm][fn][3]);
            if (do_silu){
                v0.x = silu(v0.x); v0.y = silu(v0.y);
                v1.x = silu(v1.x); v1.y = silu(v1.y);
            }
            *(float2*)(outp + (size_t)row0*HID + col)     = v0;
            *(float2*)(outp + (size_t)(row0+8)*HID + col) = v1;
        }
    }
}

// ---------------- WKV recurrence, barrier-light -----------------------------
__global__ __launch_bounds__(256) void wkv_kernel(
    const float* __restrict__ time_decay, const float* __restrict__ time_faaaa)
{
    const int head = blockIdx.x, ehalf = blockIdx.y;
    const int tid = threadIdx.x, eg = tid & 31, dg = tid >> 5;
    __shared__ float ks[16][64], rs[16][64], vs[16][32];

    float td[8], tf[8], stv[8];
    #pragma unroll
    for (int j = 0; j < 8; j++){
        int d = dg*8 + j;
        td[j] = expf(-expf(time_decay[head*HD + d]));
        tf[j] = time_faaaa[head*HD + d];
        stv[j] = 0.f;
    }
    const float* kb = g_kvrg + 0*(size_t)SZ + head*HD;
    const float* vb = g_kvrg + 1*(size_t)SZ + head*HD + ehalf*32;
    const float* rb = g_kvrg + 2*(size_t)SZ + head*HD;
    float* op = g_opart + (size_t)dg*SZ + head*HD + ehalf*32;

    const int ktrow = tid >> 4, kseg = tid & 15;
    const int vtrow = tid >> 3, vseg = tid & 7;
    float4 ka, ra, va;
    ka = *(const float4*)(kb + (size_t)ktrow*HID + kseg*4);
    ra = *(const float4*)(rb + (size_t)ktrow*HID + kseg*4);
    if (tid < 128) va = *(const float4*)(vb + (size_t)vtrow*HID + vseg*4);

    for (int c = 0; c < SEQ/16; c++){
        __syncthreads();
        *(float4*)&ks[ktrow][kseg*4] = ka;
        *(float4*)&rs[ktrow][kseg*4] = ra;
        if (tid < 128) *(float4*)&vs[vtrow][vseg*4] = va;
        __syncthreads();
        if (c < SEQ/16 - 1){
            const size_t t1 = (size_t)(c+1)*16;
            ka = *(const float4*)(kb + (t1+ktrow)*HID + kseg*4);
            ra = *(const float4*)(rb + (t1+ktrow)*HID + kseg*4);
            if (tid < 128) va = *(const float4*)(vb + (t1+vtrow)*HID + vseg*4);
        }
        #pragma unroll
        for (int tt = 0; tt < 16; tt++){
            const float ve = vs[tt][eg];
            float4 k0 = *(const float4*)&ks[tt][dg*8];
            float4 k1 = *(const float4*)&ks[tt][dg*8+4];
            float4 r0 = *(const float4*)&rs[tt][dg*8];
            float4 r1 = *(const float4*)&rs[tt][dg*8+4];
            float kv, o = 0.f;
            kv = k0.x*ve; o = fmaf(r0.x, fmaf(tf[0],kv,stv[0]), o); stv[0] = fmaf(td[0],stv[0],kv);
            kv = k0.y*ve; o = fmaf(r0.y, fmaf(tf[1],kv,stv[1]), o); stv[1] = fmaf(td[1],stv[1],kv);
            kv = k0.z*ve; o = fmaf(r0.z, fmaf(tf[2],kv,stv[2]), o); stv[2] = fmaf(td[2],stv[2],kv);
            kv = k0.w*ve; o = fmaf(r0.w, fmaf(tf[3],kv,stv[3]), o); stv[3] = fmaf(td[3],stv[3],kv);
            kv = k1.x*ve; o = fmaf(r1.x, fmaf(tf[4],kv,stv[4]), o); stv[4] = fmaf(td[4],stv[4],kv);
            kv = k1.y*ve; o = fmaf(r1.y, fmaf(tf[5],kv,stv[5]), o); stv[5] = fmaf(td[5],stv[5],kv);
            kv = k1.z*ve; o = fmaf(r1.z, fmaf(tf[6],kv,stv[6]), o); stv[6] = fmaf(td[6],stv[6],kv);
            kv = k1.w*ve; o = fmaf(r1.w, fmaf(tf[7],kv,stv[7]), o); stv[7] = fmaf(td[7],stv[7],kv);
            op[(size_t)(c*16+tt)*HID + eg] = o;
        }
    }
}

// ---------------- GroupNorm + gate + split-fp16 -----------------------------
__global__ __launch_bounds__(256) void norm_kernel(
    const float* __restrict__ gnw, const float* __restrict__ gnb)
{
    const int wid = threadIdx.x >> 5, lane = threadIdx.x & 31;
    const int g = blockIdx.x*8 + wid;
    const int t = g >> 6, h = g & 63, e0 = lane*2;
    const size_t bse = (size_t)t*HID + h*HD + e0;

    float o0 = 0.f, o1 = 0.f;
    #pragma unroll
    for (int dg = 0; dg < 8; dg++){
        float2 v = *(const float2*)(g_opart + (size_t)dg*SZ + bse);
        o0 += v.x; o1 += v.y;
    }
    float s = o0 + o1, s2 = o0*o0 + o1*o1;
    #pragma unroll
    for (int off = 16; off > 0; off >>= 1){
        s  += __shfl_xor_sync(0xffffffffu, s,  off);
        s2 += __shfl_xor_sync(0xffffffffu, s2, off);
    }
    const float mean = s * (1.f/64.f);
    const float var  = s2 * (1.f/64.f) - mean*mean;
    const float rstd = rsqrtf(var + 1e-5f);
    float2 gt = *(const float2*)(g_kvrg + 3*(size_t)SZ + bse);
    const float w0 = gnw[h*HD+e0], w1 = gnw[h*HD+e0+1];
    const float b0 = gnb[h*HD+e0], b1 = gnb[h*HD+e0+1];
    float y0 = ((o0-mean)*rstd*w0 + b0) * gt.x;
    float y1 = ((o1-mean)*rstd*w1 + b1) * gt.y;
    __half h0,h1,l0,l1;
    split_h(y0,h0,l0); split_h(y1,h1,l1);
    *(uint32_t*)(g_abh + bse) = pkh(h0,h1);
    *(uint32_t*)(g_abl + bse) = pkh(l0,l1);
}

// ---------------------------------------------------------------------------
extern "C" void kernel_launch(void* const* d_in, const int* in_sizes, int n_in,
                              void* d_out, int out_size)
{
    const float* hidden     = (const float*)d_in[0];
    const float* w_key      = (const float*)d_in[1];
    const float* w_value    = (const float*)d_in[2];
    const float* w_recept   = (const float*)d_in[3];
    const float* w_gate     = (const float*)d_in[4];
    const float* w_output   = (const float*)d_in[5];
    const float* tm_key     = (const float*)d_in[6];
    const float* tm_value   = (const float*)d_in[7];
    const float* tm_recept  = (const float*)d_in[8];
    const float* tm_gate    = (const float*)d_in[9];
    const float* time_decay = (const float*)d_in[10];
    const float* time_faaaa = (const float*)d_in[11];
    const float* gn_w       = (const float*)d_in[12];
    const float* gn_b       = (const float*)d_in[13];

    cudaFuncSetAttribute(gemm_kernel, cudaFuncAttributeMaxDynamicSharedMemorySize, GSMEM);

    dim3 gw(SZW/1024, 5);
    prepass_w_kernel<<<gw, 256>>>(w_key, w_value, w_recept, w_gate, w_output);
    prepass_kernel<<<SZ/1024, 256>>>(hidden, tm_key, tm_value, tm_recept, tm_gate);

    dim3 gproj(SEQ/128, HID/128, 4);
    gemm_kernel<<<gproj, 256, GSMEM>>>(0, nullptr);

    dim3 gwkv(NH, 2);
    wkv_kernel<<<gwkv, 256>>>(time_decay, time_faaaa);

    norm_kernel<<<SEQ*NH/8, 256>>>(gn_w, gn_b);

    dim3 gout(SEQ/128, HID/128, 1);
    gemm_kernel<<<gout, 256, GSMEM>>>(1, (float*)d_out);
}

// round 9
// speedup vs baseline: 1.4942x; 1.0017x over previous
#include <cuda_runtime.h>
#include <cuda_fp16.h>
#include <math.h>
#include <stdint.h>

#define SEQ 1024
#define HID 4096
#define NH  64
#define HD  64
#define SZ  (SEQ*HID)
#define SZW (HID*HID)

__device__ float   g_kvrg[4*SZ];     // k,v,r,g(silu) fp32
__device__ float   g_opart[8*SZ];    // WKV partials per d-group
__device__ __half  g_mAh[4*SZ];      // mixed activations hi (fp16)
__device__ __half  g_mAl[4*SZ];      // mixed activations lo (fp16)
__device__ __half  g_abh[SZ];        // normed/gated hi
__device__ __half  g_abl[SZ];        // normed/gated lo
__device__ __half  g_W[5*SZW];       // weights fp16 (k,v,r,g,o)

__device__ __forceinline__ uint32_t pkh(__half a, __half b){
    __half2 t = __halves2half2(a, b);
    return *reinterpret_cast<uint32_t*>(&t);
}
__device__ __forceinline__ void split_h(float x, __half& h, __half& l){
    h = __float2half(x);
    l = __float2half(x - __half2float(h));
}
__device__ __forceinline__ float silu(float x){ return x / (1.f + expf(-x)); }
__device__ __forceinline__ uint32_t smem_u32(const void* p){
    uint32_t a;
    asm("{ .reg .u64 t; cvta.to.shared.u64 t, %1; cvt.u32.u64 %0, t; }" : "=r"(a) : "l"(p));
    return a;
}
__device__ __forceinline__ void mma16816(float* c, const uint32_t* a, uint32_t b0, uint32_t b1){
    asm volatile("mma.sync.aligned.m16n8k16.row.col.f32.f16.f16.f32 "
        "{%0,%1,%2,%3}, {%4,%5,%6,%7}, {%8,%9}, {%0,%1,%2,%3};"
        : "+f"(c[0]), "+f"(c[1]), "+f"(c[2]), "+f"(c[3])
        : "r"(a[0]), "r"(a[1]), "r"(a[2]), "r"(a[3]), "r"(b0), "r"(b1));
}
__device__ __forceinline__ void ldsm4(uint32_t* r, uint32_t a){
    asm volatile("ldmatrix.sync.aligned.m8n8.x4.shared.b16 {%0,%1,%2,%3}, [%4];"
        : "=r"(r[0]), "=r"(r[1]), "=r"(r[2]), "=r"(r[3]) : "r"(a));
}
__device__ __forceinline__ void ldsm2(uint32_t* r, uint32_t a){
    asm volatile("ldmatrix.sync.aligned.m8n8.x2.shared.b16 {%0,%1}, [%2];"
        : "=r"(r[0]), "=r"(r[1]) : "r"(a));
}
__device__ __forceinline__ void cpa16(uint32_t dst, const void* src){
    asm volatile("cp.async.cg.shared.global [%0], [%1], 16;" :: "r"(dst), "l"(src));
}
#define CPA_COMMIT() asm volatile("cp.async.commit_group;" ::: "memory")
#define CPA_WAIT1()  asm volatile("cp.async.wait_group 1;" ::: "memory")

// ---------------- weight prepass: fp32 -> fp16 ------------------------------
__global__ __launch_bounds__(256) void prepass_w_kernel(
    const float* __restrict__ wk, const float* __restrict__ wv,
    const float* __restrict__ wr, const float* __restrict__ wg,
    const float* __restrict__ wo)
{
    const int p = blockIdx.y;
    const float* W = (p==0)?wk:(p==1)?wv:(p==2)?wr:(p==3)?wg:wo;
    size_t idx = ((size_t)blockIdx.x*256 + threadIdx.x)*4;
    float4 w4 = *(const float4*)(W + idx);
    *(uint2*)(g_W + (size_t)p*SZW + idx) =
        make_uint2(pkh(__float2half(w4.x), __float2half(w4.y)),
                   pkh(__float2half(w4.z), __float2half(w4.w)));
}

// ---------------- activation prepass: mix -> split fp16 ---------------------
__global__ __launch_bounds__(256) void prepass_kernel(
    const float* __restrict__ hidden, const float* __restrict__ mk,
    const float* __restrict__ mv, const float* __restrict__ mr, const float* __restrict__ mg)
{
    int idx = (blockIdx.x*256 + threadIdx.x)*4;
    int t = idx >> 12, c = idx & 4095;
    float4 hv = *(const float4*)(hidden + idx);
    float4 sv = make_float4(0.f,0.f,0.f,0.f);
    if (t > 0) sv = *(const float4*)(hidden + idx - HID);
    const float* ms[4] = {mk, mv, mr, mg};
    #pragma unroll
    for (int p = 0; p < 4; p++){
        float4 m = *(const float4*)(ms[p] + c);
        float x0 = hv.x*m.x + sv.x*(1.f-m.x), x1 = hv.y*m.y + sv.y*(1.f-m.y);
        float x2 = hv.z*m.z + sv.z*(1.f-m.z), x3 = hv.w*m.w + sv.w*(1.f-m.w);
        __half h0,h1,h2,h3,l0,l1,l2,l3;
        split_h(x0,h0,l0); split_h(x1,h1,l1); split_h(x2,h2,l2); split_h(x3,h3,l3);
        *(uint2*)(g_mAh + (size_t)p*SZ + idx) = make_uint2(pkh(h0,h1), pkh(h2,h3));
        *(uint2*)(g_mAl + (size_t)p*SZ + idx) = make_uint2(pkh(l0,l1), pkh(l2,l3));
    }
}

// ---------------- mma.sync GEMM, 3-stage cp.async pipeline ------------------
// C[M,N] = A[M,K] * W[N,K]^T.  Tile 128x128, KC=64, 8 warps (4m x 2n).
// fp16 2-term: C = Ah*B + Al*B ; MMAs issued as two independent 16-acc sweeps
#define KC 64
#define SP 72
#define TH (128*SP)              // elems per tile-half
#define NSTAGE 3
#define GSMEM (NSTAGE*3*TH*2)    // bytes: Ah | Al | B per stage

__global__ __launch_bounds__(256) void gemm_kernel(int mode, float* __restrict__ dout)
{
    extern __shared__ __half sm[];
    const int tid = threadIdx.x, z = blockIdx.z;
    const __half *AhG, *AlG, *BG;
    float* outp;
    bool do_silu = false;
    if (mode == 0){
        AhG = g_mAh + (size_t)z*SZ; AlG = g_mAl + (size_t)z*SZ;
        BG  = g_W + (size_t)z*SZW;
        outp = g_kvrg + (size_t)z*SZ; do_silu = (z==3);
    } else {
        AhG = g_abh; AlG = g_abl;
        BG  = g_W + 4*(size_t)SZW;
        outp = dout;
    }

    const int m0 = blockIdx.x*128, n0 = blockIdx.y*128;
    const int wid = tid>>5, lane = tid&31;
    const int wm = (wid&3)*32, wn = (wid>>2)*64;
    const int r = lane>>2, q = lane&3;
    const uint32_t sbase = smem_u32(sm);

    const int crow = tid>>3, cseg = tid&7;          // copy: 32 rows x 8 segs / 256 thr
    const size_t gAoff = (size_t)(m0+crow)*HID + cseg*8;
    const size_t gBoff = (size_t)(n0+crow)*HID + cseg*8;
    const uint32_t soff = (uint32_t)(crow*SP + cseg*8)*2;

    float acc[2][8][4];
    #pragma unroll
    for (int i=0;i<2;i++)
        #pragma unroll
        for (int j=0;j<8;j++)
            #pragma unroll
            for (int k=0;k<4;k++) acc[i][j][k]=0.f;

    auto issue = [&](int c, int s){
        const int k0 = c*KC;
        const uint32_t st = sbase + (uint32_t)(s*3*TH)*2;
        #pragma unroll
        for (int i = 0; i < 4; i++){
            const uint32_t dof = soff + (uint32_t)(i*32*SP)*2;
            const size_t ga = gAoff + k0 + (size_t)i*32*HID;
            const size_t gb = gBoff + k0 + (size_t)i*32*HID;
            cpa16(st + dof,                    AhG + ga);
            cpa16(st + (uint32_t)TH*2   + dof, AlG + ga);
            cpa16(st + (uint32_t)2*TH*2 + dof, BG  + gb);
        }
    };

    issue(0, 0); CPA_COMMIT();
    issue(1, 1); CPA_COMMIT();

    const int NCH = HID/KC;
    for (int c = 0; c < NCH; c++){
        const int s = c % NSTAGE;
        CPA_WAIT1();
        __syncthreads();
        if (c + 2 < NCH) issue(c + 2, (c + 2) % NSTAGE);
        CPA_COMMIT();

        const uint32_t stA_h = sbase + (uint32_t)(s*3*TH)*2;
        const uint32_t stA_l = stA_h + (uint32_t)TH*2;
        const uint32_t stB   = stA_h + (uint32_t)2*TH*2;

        #pragma unroll
        for (int ko = 0; ko < KC; ko += 16){
            uint32_t ah[2][4], al[2][4], bb[8][2];
            const int arow = wm + (lane&15), acol = ko + (lane>>4)*8;
            #pragma unroll
            for (int fm = 0; fm < 2; fm++){
                const uint32_t ao = (uint32_t)((arow + fm*16)*SP + acol)*2;
                ldsm4(ah[fm], stA_h + ao);
                ldsm4(al[fm], stA_l + ao);
            }
            const int brow = wn + (lane&7), bcol = ko + ((lane>>3)&1)*8;
            #pragma unroll
            for (int fn = 0; fn < 8; fn++){
                const uint32_t bo = (uint32_t)((brow + fn*8)*SP + bcol)*2;
                ldsm2(bb[fn], stB + bo);
            }
            // sweep 1: Ah*B over 16 independent accumulators
            #pragma unroll
            for (int fn = 0; fn < 8; fn++)
                #pragma unroll
                for (int fm = 0; fm < 2; fm++)
                    mma16816(acc[fm][fn], ah[fm], bb[fn][0], bb[fn][1]);
            // sweep 2: Al*B over the same 16 accumulators
            #pragma unroll
            for (int fn = 0; fn < 8; fn++)
                #pragma unroll
                for (int fm = 0; fm < 2; fm++)
                    mma16816(acc[fm][fn], al[fm], bb[fn][0], bb[fn][1]);
        }
        __syncthreads();
    }

    #pragma unroll
    for (int fm = 0; fm < 2; fm++){
        #pragma unroll
        for (int fn = 0; fn < 8; fn++){
            int row0 = m0 + wm + fm*16 + r;
            int col  = n0 + wn + fn*8 + q*2;
            float2 v0 = make_float2(acc[fm][fn][0], acc[fm][fn][1]);
            float2 v1 = make_float2(acc[fm][fn][2], acc[fm][fn][3]);
            if (do_silu){
                v0.x = silu(v0.x); v0.y = silu(v0.y);
                v1.x = silu(v1.x); v1.y = silu(v1.y);
            }
            *(float2*)(outp + (size_t)row0*HID + col)     = v0;
            *(float2*)(outp + (size_t)(row0+8)*HID + col) = v1;
        }
    }
}

// ---------------- WKV recurrence, barrier-light -----------------------------
__global__ __launch_bounds__(256) void wkv_kernel(
    const float* __restrict__ time_decay, const float* __restrict__ time_faaaa)
{
    const int head = blockIdx.x, ehalf = blockIdx.y;
    const int tid = threadIdx.x, eg = tid & 31, dg = tid >> 5;
    __shared__ float ks[16][64], rs[16][64], vs[16][32];

    float td[8], tf[8], stv[8];
    #pragma unroll
    for (int j = 0; j < 8; j++){
        int d = dg*8 + j;
        td[j] = expf(-expf(time_decay[head*HD + d]));
        tf[j] = time_faaaa[head*HD + d];
        stv[j] = 0.f;
    }
    const float* kb = g_kvrg + 0*(size_t)SZ + head*HD;
    const float* vb = g_kvrg + 1*(size_t)SZ + head*HD + ehalf*32;
    const float* rb = g_kvrg + 2*(size_t)SZ + head*HD;
    float* op = g_opart + (size_t)dg*SZ + head*HD + ehalf*32;

    const int ktrow = tid >> 4, kseg = tid & 15;
    const int vtrow = tid >> 3, vseg = tid & 7;
    float4 ka, ra, va;
    ka = *(const float4*)(kb + (size_t)ktrow*HID + kseg*4);
    ra = *(const float4*)(rb + (size_t)ktrow*HID + kseg*4);
    if (tid < 128) va = *(const float4*)(vb + (size_t)vtrow*HID + vseg*4);

    for (int c = 0; c < SEQ/16; c++){
        __syncthreads();
        *(float4*)&ks[ktrow][kseg*4] = ka;
        *(float4*)&rs[ktrow][kseg*4] = ra;
        if (tid < 128) *(float4*)&vs[vtrow][vseg*4] = va;
        __syncthreads();
        if (c < SEQ/16 - 1){
            const size_t t1 = (size_t)(c+1)*16;
            ka = *(const float4*)(kb + (t1+ktrow)*HID + kseg*4);
            ra = *(const float4*)(rb + (t1+ktrow)*HID + kseg*4);
            if (tid < 128) va = *(const float4*)(vb + (t1+vtrow)*HID + vseg*4);
        }
        #pragma unroll
        for (int tt = 0; tt < 16; tt++){
            const float ve = vs[tt][eg];
            float4 k0 = *(const float4*)&ks[tt][dg*8];
            float4 k1 = *(const float4*)&ks[tt][dg*8+4];
            float4 r0 = *(const float4*)&rs[tt][dg*8];
            float4 r1 = *(const float4*)&rs[tt][dg*8+4];
            float kv, o = 0.f;
            kv = k0.x*ve; o = fmaf(r0.x, fmaf(tf[0],kv,stv[0]), o); stv[0] = fmaf(td[0],stv[0],kv);
            kv = k0.y*ve; o = fmaf(r0.y, fmaf(tf[1],kv,stv[1]), o); stv[1] = fmaf(td[1],stv[1],kv);
            kv = k0.z*ve; o = fmaf(r0.z, fmaf(tf[2],kv,stv[2]), o); stv[2] = fmaf(td[2],stv[2],kv);
            kv = k0.w*ve; o = fmaf(r0.w, fmaf(tf[3],kv,stv[3]), o); stv[3] = fmaf(td[3],stv[3],kv);
            kv = k1.x*ve; o = fmaf(r1.x, fmaf(tf[4],kv,stv[4]), o); stv[4] = fmaf(td[4],stv[4],kv);
            kv = k1.y*ve; o = fmaf(r1.y, fmaf(tf[5],kv,stv[5]), o); stv[5] = fmaf(td[5],stv[5],kv);
            kv = k1.z*ve; o = fmaf(r1.z, fmaf(tf[6],kv,stv[6]), o); stv[6] = fmaf(td[6],stv[6],kv);
            kv = k1.w*ve; o = fmaf(r1.w, fmaf(tf[7],kv,stv[7]), o); stv[7] = fmaf(td[7],stv[7],kv);
            op[(size_t)(c*16+tt)*HID + eg] = o;
        }
    }
}

// ---------------- GroupNorm + gate + split-fp16 -----------------------------
__global__ __launch_bounds__(256) void norm_kernel(
    const float* __restrict__ gnw, const float* __restrict__ gnb)
{
    const int wid = threadIdx.x >> 5, lane = threadIdx.x & 31;
    const int g = blockIdx.x*8 + wid;
    const int t = g >> 6, h = g & 63, e0 = lane*2;
    const size_t bse = (size_t)t*HID + h*HD + e0;

    float o0 = 0.f, o1 = 0.f;
    #pragma unroll
    for (int dg = 0; dg < 8; dg++){
        float2 v = *(const float2*)(g_opart + (size_t)dg*SZ + bse);
        o0 += v.x; o1 += v.y;
    }
    float s = o0 + o1, s2 = o0*o0 + o1*o1;
    #pragma unroll
    for (int off = 16; off > 0; off >>= 1){
        s  += __shfl_xor_sync(0xffffffffu, s,  off);
        s2 += __shfl_xor_sync(0xffffffffu, s2, off);
    }
    const float mean = s * (1.f/64.f);
    const float var  = s2 * (1.f/64.f) - mean*mean;
    const float rstd = rsqrtf(var + 1e-5f);
    float2 gt = *(const float2*)(g_kvrg + 3*(size_t)SZ + bse);
    const float w0 = gnw[h*HD+e0], w1 = gnw[h*HD+e0+1];
    const float b0 = gnb[h*HD+e0], b1 = gnb[h*HD+e0+1];
    float y0 = ((o0-mean)*rstd*w0 + b0) * gt.x;
    float y1 = ((o1-mean)*rstd*w1 + b1) * gt.y;
    __half h0,h1,l0,l1;
    split_h(y0,h0,l0); split_h(y1,h1,l1);
    *(uint32_t*)(g_abh + bse) = pkh(h0,h1);
    *(uint32_t*)(g_abl + bse) = pkh(l0,l1);
}

// ---------------------------------------------------------------------------
extern "C" void kernel_launch(void* const* d_in, const int* in_sizes, int n_in,
                              void* d_out, int out_size)
{
    const float* hidden     = (const float*)d_in[0];
    const float* w_key      = (const float*)d_in[1];
    const float* w_value    = (const float*)d_in[2];
    const float* w_recept   = (const float*)d_in[3];
    const float* w_gate     = (const float*)d_in[4];
    const float* w_output   = (const float*)d_in[5];
    const float* tm_key     = (const float*)d_in[6];
    const float* tm_value   = (const float*)d_in[7];
    const float* tm_recept  = (const float*)d_in[8];
    const float* tm_gate    = (const float*)d_in[9];
    const float* time_decay = (const float*)d_in[10];
    const float* time_faaaa = (const float*)d_in[11];
    const float* gn_w       = (const float*)d_in[12];
    const float* gn_b       = (const float*)d_in[13];

    cudaFuncSetAttribute(gemm_kernel, cudaFuncAttributeMaxDynamicSharedMemorySize, GSMEM);

    dim3 gw(SZW/1024, 5);
    prepass_w_kernel<<<gw, 256>>>(w_key, w_value, w_recept, w_gate, w_output);
    prepass_kernel<<<SZ/1024, 256>>>(hidden, tm_key, tm_value, tm_recept, tm_gate);

    dim3 gproj(SEQ/128, HID/128, 4);
    gemm_kernel<<<gproj, 256, GSMEM>>>(0, nullptr);

    dim3 gwkv(NH, 2);
    wkv_kernel<<<gwkv, 256>>>(time_decay, time_faaaa);

    norm_kernel<<<SEQ*NH/8, 256>>>(gn_w, gn_b);

    dim3 gout(SEQ/128, HID/128, 1);
    gemm_kernel<<<gout, 256, GSMEM>>>(1, (float*)d_out);
}

// round 10
// speedup vs baseline: 2.1861x; 1.4631x over previous
#include <cuda_runtime.h>
#include <cuda_fp16.h>
#include <math.h>
#include <stdint.h>

#define SEQ 1024
#define HID 4096
#define NH  64
#define HD  64
#define SZ  (SEQ*HID)
#define SZW (HID*HID)

__device__ float   g_kvrg[4*SZ];     // k,v,r,g(silu) fp32
__device__ float   g_opart[8*SZ];    // WKV partials per d-group
__device__ __half  g_mA[4*SZ];       // mixed activations fp16 (RN)
__device__ __half  g_abh[SZ];        // normed/gated hi
__device__ __half  g_abl[SZ];        // normed/gated lo
__device__ __half  g_W[5*SZW];       // weights fp16 (k,v,r,g,o)

__device__ __forceinline__ uint32_t pkh(__half a, __half b){
    __half2 t = __halves2half2(a, b);
    return *reinterpret_cast<uint32_t*>(&t);
}
__device__ __forceinline__ void split_h(float x, __half& h, __half& l){
    h = __float2half(x);
    l = __float2half(x - __half2float(h));
}
__device__ __forceinline__ float silu(float x){ return x / (1.f + expf(-x)); }
__device__ __forceinline__ uint32_t smem_u32(const void* p){
    uint32_t a;
    asm("{ .reg .u64 t; cvta.to.shared.u64 t, %1; cvt.u32.u64 %0, t; }" : "=r"(a) : "l"(p));
    return a;
}
__device__ __forceinline__ void mma16816(float* c, const uint32_t* a, uint32_t b0, uint32_t b1){
    asm volatile("mma.sync.aligned.m16n8k16.row.col.f32.f16.f16.f32 "
        "{%0,%1,%2,%3}, {%4,%5,%6,%7}, {%8,%9}, {%0,%1,%2,%3};"
        : "+f"(c[0]), "+f"(c[1]), "+f"(c[2]), "+f"(c[3])
        : "r"(a[0]), "r"(a[1]), "r"(a[2]), "r"(a[3]), "r"(b0), "r"(b1));
}
__device__ __forceinline__ void ldsm4(uint32_t* r, uint32_t a){
    asm volatile("ldmatrix.sync.aligned.m8n8.x4.shared.b16 {%0,%1,%2,%3}, [%4];"
        : "=r"(r[0]), "=r"(r[1]), "=r"(r[2]), "=r"(r[3]) : "r"(a));
}
__device__ __forceinline__ void ldsm2(uint32_t* r, uint32_t a){
    asm volatile("ldmatrix.sync.aligned.m8n8.x2.shared.b16 {%0,%1}, [%2];"
        : "=r"(r[0]), "=r"(r[1]) : "r"(a));
}
__device__ __forceinline__ void cpa16(uint32_t dst, const void* src){
    asm volatile("cp.async.cg.shared.global [%0], [%1], 16;" :: "r"(dst), "l"(src));
}
#define CPA_COMMIT() asm volatile("cp.async.commit_group;" ::: "memory")
#define CPA_WAIT1()  asm volatile("cp.async.wait_group 1;" ::: "memory")

// ---------------- weight prepass: fp32 -> fp16 ------------------------------
__global__ __launch_bounds__(256) void prepass_w_kernel(
    const float* __restrict__ wk, const float* __restrict__ wv,
    const float* __restrict__ wr, const float* __restrict__ wg,
    const float* __restrict__ wo)
{
    const int p = blockIdx.y;
    const float* W = (p==0)?wk:(p==1)?wv:(p==2)?wr:(p==3)?wg:wo;
    size_t idx = ((size_t)blockIdx.x*256 + threadIdx.x)*4;
    float4 w4 = *(const float4*)(W + idx);
    *(uint2*)(g_W + (size_t)p*SZW + idx) =
        make_uint2(pkh(__float2half(w4.x), __float2half(w4.y)),
                   pkh(__float2half(w4.z), __float2half(w4.w)));
}

// ---------------- activation prepass: mix -> fp16 (RN) ----------------------
__global__ __launch_bounds__(256) void prepass_kernel(
    const float* __restrict__ hidden, const float* __restrict__ mk,
    const float* __restrict__ mv, const float* __restrict__ mr, const float* __restrict__ mg)
{
    int idx = (blockIdx.x*256 + threadIdx.x)*4;
    int t = idx >> 12, c = idx & 4095;
    float4 hv = *(const float4*)(hidden + idx);
    float4 sv = make_float4(0.f,0.f,0.f,0.f);
    if (t > 0) sv = *(const float4*)(hidden + idx - HID);
    const float* ms[4] = {mk, mv, mr, mg};
    #pragma unroll
    for (int p = 0; p < 4; p++){
        float4 m = *(const float4*)(ms[p] + c);
        float x0 = hv.x*m.x + sv.x*(1.f-m.x), x1 = hv.y*m.y + sv.y*(1.f-m.y);
        float x2 = hv.z*m.z + sv.z*(1.f-m.z), x3 = hv.w*m.w + sv.w*(1.f-m.w);
        *(uint2*)(g_mA + (size_t)p*SZ + idx) =
            make_uint2(pkh(__float2half(x0), __float2half(x1)),
                       pkh(__float2half(x2), __float2half(x3)));
    }
}

// ---------------- mma.sync GEMM, 3-stage cp.async pipeline ------------------
// C[M,N] = A[M,K] * W[N,K]^T.  Tile 128x128, KC=64, 8 warps (4m x 2n).
// TERMS=1: C = A*B (proj).  TERMS=2: C = Ah*B + Al*B (out GEMM).
#define KC 64
#define SP 72
#define TH (128*SP)              // elems per tile
#define NSTAGE 3

template<int TERMS>
__global__ __launch_bounds__(256) void gemm_kernel(float* __restrict__ dout)
{
    extern __shared__ __half sm[];
    const int tid = threadIdx.x, z = blockIdx.z;
    const __half *AhG, *AlG, *BG;
    float* outp;
    bool do_silu = false;
    if (TERMS == 1){
        AhG = g_mA + (size_t)z*SZ; AlG = nullptr;
        BG  = g_W + (size_t)z*SZW;
        outp = g_kvrg + (size_t)z*SZ; do_silu = (z==3);
    } else {
        AhG = g_abh; AlG = g_abl;
        BG  = g_W + 4*(size_t)SZW;
        outp = dout;
    }
    const int TPS = TERMS + 1;   // tiles per stage

    const int m0 = blockIdx.x*128, n0 = blockIdx.y*128;
    const int wid = tid>>5, lane = tid&31;
    const int wm = (wid&3)*32, wn = (wid>>2)*64;
    const int r = lane>>2, q = lane&3;
    const uint32_t sbase = smem_u32(sm);

    const int crow = tid>>3, cseg = tid&7;          // copy: 32 rows x 8 segs / 256 thr
    const size_t gAoff = (size_t)(m0+crow)*HID + cseg*8;
    const size_t gBoff = (size_t)(n0+crow)*HID + cseg*8;
    const uint32_t soff = (uint32_t)(crow*SP + cseg*8)*2;

    float acc[2][8][4];
    #pragma unroll
    for (int i=0;i<2;i++)
        #pragma unroll
        for (int j=0;j<8;j++)
            #pragma unroll
            for (int k=0;k<4;k++) acc[i][j][k]=0.f;

    auto issue = [&](int c, int s){
        const int k0 = c*KC;
        const uint32_t st = sbase + (uint32_t)(s*TPS*TH)*2;
        #pragma unroll
        for (int i = 0; i < 4; i++){
            const uint32_t dof = soff + (uint32_t)(i*32*SP)*2;
            const size_t ga = gAoff + k0 + (size_t)i*32*HID;
            const size_t gb = gBoff + k0 + (size_t)i*32*HID;
            cpa16(st + dof, AhG + ga);
            if (TERMS == 2) cpa16(st + (uint32_t)TH*2 + dof, AlG + ga);
            cpa16(st + (uint32_t)(TERMS)*TH*2 + dof, BG + gb);
        }
    };

    issue(0, 0); CPA_COMMIT();
    issue(1, 1); CPA_COMMIT();

    const int NCH = HID/KC;
    for (int c = 0; c < NCH; c++){
        const int s = c % NSTAGE;
        CPA_WAIT1();
        __syncthreads();
        if (c + 2 < NCH) issue(c + 2, (c + 2) % NSTAGE);
        CPA_COMMIT();

        const uint32_t stA_h = sbase + (uint32_t)(s*TPS*TH)*2;
        const uint32_t stA_l = stA_h + (uint32_t)TH*2;
        const uint32_t stB   = stA_h + (uint32_t)(TERMS)*TH*2;

        #pragma unroll
        for (int ko = 0; ko < KC; ko += 16){
            uint32_t ah[2][4], al[2][4], bb[8][2];
            const int arow = wm + (lane&15), acol = ko + (lane>>4)*8;
            #pragma unroll
            for (int fm = 0; fm < 2; fm++){
                const uint32_t ao = (uint32_t)((arow + fm*16)*SP + acol)*2;
                ldsm4(ah[fm], stA_h + ao);
                if (TERMS == 2) ldsm4(al[fm], stA_l + ao);
            }
            const int brow = wn + (lane&7), bcol = ko + ((lane>>3)&1)*8;
            #pragma unroll
            for (int fn = 0; fn < 8; fn++){
                const uint32_t bo = (uint32_t)((brow + fn*8)*SP + bcol)*2;
                ldsm2(bb[fn], stB + bo);
            }
            #pragma unroll
            for (int fn = 0; fn < 8; fn++)
                #pragma unroll
                for (int fm = 0; fm < 2; fm++)
                    mma16816(acc[fm][fn], ah[fm], bb[fn][0], bb[fn][1]);
            if (TERMS == 2){
                #pragma unroll
                for (int fn = 0; fn < 8; fn++)
                    #pragma unroll
                    for (int fm = 0; fm < 2; fm++)
                        mma16816(acc[fm][fn], al[fm], bb[fn][0], bb[fn][1]);
            }
        }
        __syncthreads();
    }

    #pragma unroll
    for (int fm = 0; fm < 2; fm++){
        #pragma unroll
        for (int fn = 0; fn < 8; fn++){
            int row0 = m0 + wm + fm*16 + r;
            int col  = n0 + wn + fn*8 + q*2;
            float2 v0 = make_float2(acc[fm][fn][0], acc[fm][fn][1]);
            float2 v1 = make_float2(acc[fm][fn][2], acc[fm][fn][3]);
            if (do_silu){
                v0.x = silu(v0.x); v0.y = silu(v0.y);
                v1.x = silu(v1.x); v1.y = silu(v1.y);
            }
            *(float2*)(outp + (size_t)row0*HID + col)     = v0;
            *(float2*)(outp + (size_t)(row0+8)*HID + col) = v1;
        }
    }
}

// ---------------- WKV recurrence, barrier-light -----------------------------
__global__ __launch_bounds__(256) void wkv_kernel(
    const float* __restrict__ time_decay, const float* __restrict__ time_faaaa)
{
    const int head = blockIdx.x, ehalf = blockIdx.y;
    const int tid = threadIdx.x, eg = tid & 31, dg = tid >> 5;
    __shared__ float ks[16][64], rs[16][64], vs[16][32];

    float td[8], tf[8], stv[8];
    #pragma unroll
    for (int j = 0; j < 8; j++){
        int d = dg*8 + j;
        td[j] = expf(-expf(time_decay[head*HD + d]));
        tf[j] = time_faaaa[head*HD + d];
        stv[j] = 0.f;
    }
    const float* kb = g_kvrg + 0*(size_t)SZ + head*HD;
    const float* vb = g_kvrg + 1*(size_t)SZ + head*HD + ehalf*32;
    const float* rb = g_kvrg + 2*(size_t)SZ + head*HD;
    float* op = g_opart + (size_t)dg*SZ + head*HD + ehalf*32;

    const int ktrow = tid >> 4, kseg = tid & 15;
    const int vtrow = tid >> 3, vseg = tid & 7;
    float4 ka, ra, va;
    ka = *(const float4*)(kb + (size_t)ktrow*HID + kseg*4);
    ra = *(const float4*)(rb + (size_t)ktrow*HID + kseg*4);
    if (tid < 128) va = *(const float4*)(vb + (size_t)vtrow*HID + vseg*4);

    for (int c = 0; c < SEQ/16; c++){
        __syncthreads();
        *(float4*)&ks[ktrow][kseg*4] = ka;
        *(float4*)&rs[ktrow][kseg*4] = ra;
        if (tid < 128) *(float4*)&vs[vtrow][vseg*4] = va;
        __syncthreads();
        if (c < SEQ/16 - 1){
            const size_t t1 = (size_t)(c+1)*16;
            ka = *(const float4*)(kb + (t1+ktrow)*HID + kseg*4);
            ra = *(const float4*)(rb + (t1+ktrow)*HID + kseg*4);
            if (tid < 128) va = *(const float4*)(vb + (t1+vtrow)*HID + vseg*4);
        }
        #pragma unroll
        for (int tt = 0; tt < 16; tt++){
            const float ve = vs[tt][eg];
            float4 k0 = *(const float4*)&ks[tt][dg*8];
            float4 k1 = *(const float4*)&ks[tt][dg*8+4];
            float4 r0 = *(const float4*)&rs[tt][dg*8];
            float4 r1 = *(const float4*)&rs[tt][dg*8+4];
            float kv, o = 0.f;
            kv = k0.x*ve; o = fmaf(r0.x, fmaf(tf[0],kv,stv[0]), o); stv[0] = fmaf(td[0],stv[0],kv);
            kv = k0.y*ve; o = fmaf(r0.y, fmaf(tf[1],kv,stv[1]), o); stv[1] = fmaf(td[1],stv[1],kv);
            kv = k0.z*ve; o = fmaf(r0.z, fmaf(tf[2],kv,stv[2]), o); stv[2] = fmaf(td[2],stv[2],kv);
            kv = k0.w*ve; o = fmaf(r0.w, fmaf(tf[3],kv,stv[3]), o); stv[3] = fmaf(td[3],stv[3],kv);
            kv = k1.x*ve; o = fmaf(r1.x, fmaf(tf[4],kv,stv[4]), o); stv[4] = fmaf(td[4],stv[4],kv);
            kv = k1.y*ve; o = fmaf(r1.y, fmaf(tf[5],kv,stv[5]), o); stv[5] = fmaf(td[5],stv[5],kv);
            kv = k1.z*ve; o = fmaf(r1.z, fmaf(tf[6],kv,stv[6]), o); stv[6] = fmaf(td[6],stv[6],kv);
            kv = k1.w*ve; o = fmaf(r1.w, fmaf(tf[7],kv,stv[7]), o); stv[7] = fmaf(td[7],stv[7],kv);
            op[(size_t)(c*16+tt)*HID + eg] = o;
        }
    }
}

// ---------------- GroupNorm + gate + split-fp16 -----------------------------
__global__ __launch_bounds__(256) void norm_kernel(
    const float* __restrict__ gnw, const float* __restrict__ gnb)
{
    const int wid = threadIdx.x >> 5, lane = threadIdx.x & 31;
    const int g = blockIdx.x*8 + wid;
    const int t = g >> 6, h = g & 63, e0 = lane*2;
    const size_t bse = (size_t)t*HID + h*HD + e0;

    float o0 = 0.f, o1 = 0.f;
    #pragma unroll
    for (int dg = 0; dg < 8; dg++){
        float2 v = *(const float2*)(g_opart + (size_t)dg*SZ + bse);
        o0 += v.x; o1 += v.y;
    }
    float s = o0 + o1, s2 = o0*o0 + o1*o1;
    #pragma unroll
    for (int off = 16; off > 0; off >>= 1){
        s  += __shfl_xor_sync(0xffffffffu, s,  off);
        s2 += __shfl_xor_sync(0xffffffffu, s2, off);
    }
    const float mean = s * (1.f/64.f);
    const float var  = s2 * (1.f/64.f) - mean*mean;
    const float rstd = rsqrtf(var + 1e-5f);
    float2 gt = *(const float2*)(g_kvrg + 3*(size_t)SZ + bse);
    const float w0 = gnw[h*HD+e0], w1 = gnw[h*HD+e0+1];
    const float b0 = gnb[h*HD+e0], b1 = gnb[h*HD+e0+1];
    float y0 = ((o0-mean)*rstd*w0 + b0) * gt.x;
    float y1 = ((o1-mean)*rstd*w1 + b1) * gt.y;
    __half h0,h1,l0,l1;
    split_h(y0,h0,l0); split_h(y1,h1,l1);
    *(uint32_t*)(g_abh + bse) = pkh(h0,h1);
    *(uint32_t*)(g_abl + bse) = pkh(l0,l1);
}

// ---------------------------------------------------------------------------
extern "C" void kernel_launch(void* const* d_in, const int* in_sizes, int n_in,
                              void* d_out, int out_size)
{
    const float* hidden     = (const float*)d_in[0];
    const float* w_key      = (const float*)d_in[1];
    const float* w_value    = (const float*)d_in[2];
    const float* w_recept   = (const float*)d_in[3];
    const float* w_gate     = (const float*)d_in[4];
    const float* w_output   = (const float*)d_in[5];
    const float* tm_key     = (const float*)d_in[6];
    const float* tm_value   = (const float*)d_in[7];
    const float* tm_recept  = (const float*)d_in[8];
    const float* tm_gate    = (const float*)d_in[9];
    const float* time_decay = (const float*)d_in[10];
    const float* time_faaaa = (const float*)d_in[11];
    const float* gn_w       = (const float*)d_in[12];
    const float* gn_b       = (const float*)d_in[13];

    const int smem1 = NSTAGE*2*TH*2;   // proj: A | B per stage
    const int smem2 = NSTAGE*3*TH*2;   // out:  Ah | Al | B per stage
    cudaFuncSetAttribute(gemm_kernel<1>, cudaFuncAttributeMaxDynamicSharedMemorySize, smem1);
    cudaFuncSetAttribute(gemm_kernel<2>, cudaFuncAttributeMaxDynamicSharedMemorySize, smem2);

    dim3 gw(SZW/1024, 5);
    prepass_w_kernel<<<gw, 256>>>(w_key, w_value, w_recept, w_gate, w_output);
    prepass_kernel<<<SZ/1024, 256>>>(hidden, tm_key, tm_value, tm_recept, tm_gate);

    dim3 gproj(SEQ/128, HID/128, 4);
    gemm_kernel<1><<<gproj, 256, smem1>>>(nullptr);

    dim3 gwkv(NH, 2);
    wkv_kernel<<<gwkv, 256>>>(time_decay, time_faaaa);

    norm_kernel<<<SEQ*NH/8, 256>>>(gn_w, gn_b);

    dim3 gout(SEQ/128, HID/128, 1);
    gemm_kernel<2><<<gout, 256, smem2>>>((float*)d_out);
}

// round 11
// speedup vs baseline: 2.5545x; 1.1685x over previous
#include <cuda_runtime.h>
#include <cuda_fp16.h>
#include <math.h>
#include <stdint.h>

#define SEQ 1024
#define HID 4096
#define NH  64
#define HD  64
#define SZ  (SEQ*HID)
#define SZW (HID*HID)

__device__ float   g_kvrg[4*SZ];     // k,v,r,g(silu) fp32
__device__ float   g_opart[8*SZ];    // WKV partials per d-group
__device__ __half  g_mA[4*SZ];       // mixed activations fp16 (RN)
__device__ __half  g_ab[SZ];         // normed/gated fp16
__device__ __half  g_W[5*SZW];       // weights fp16 (k,v,r,g,o)

__device__ __forceinline__ uint32_t pkh(__half a, __half b){
    __half2 t = __halves2half2(a, b);
    return *reinterpret_cast<uint32_t*>(&t);
}
__device__ __forceinline__ float silu(float x){ return x / (1.f + expf(-x)); }
__device__ __forceinline__ uint32_t smem_u32(const void* p){
    uint32_t a;
    asm("{ .reg .u64 t; cvta.to.shared.u64 t, %1; cvt.u32.u64 %0, t; }" : "=r"(a) : "l"(p));
    return a;
}
__device__ __forceinline__ void mma16816(float* c, const uint32_t* a, uint32_t b0, uint32_t b1){
    asm volatile("mma.sync.aligned.m16n8k16.row.col.f32.f16.f16.f32 "
        "{%0,%1,%2,%3}, {%4,%5,%6,%7}, {%8,%9}, {%0,%1,%2,%3};"
        : "+f"(c[0]), "+f"(c[1]), "+f"(c[2]), "+f"(c[3])
        : "r"(a[0]), "r"(a[1]), "r"(a[2]), "r"(a[3]), "r"(b0), "r"(b1));
}
__device__ __forceinline__ void ldsm4(uint32_t* r, uint32_t a){
    asm volatile("ldmatrix.sync.aligned.m8n8.x4.shared.b16 {%0,%1,%2,%3}, [%4];"
        : "=r"(r[0]), "=r"(r[1]), "=r"(r[2]), "=r"(r[3]) : "r"(a));
}
__device__ __forceinline__ void ldsm2(uint32_t* r, uint32_t a){
    asm volatile("ldmatrix.sync.aligned.m8n8.x2.shared.b16 {%0,%1}, [%2];"
        : "=r"(r[0]), "=r"(r[1]) : "r"(a));
}
__device__ __forceinline__ void cpa16(uint32_t dst, const void* src){
    asm volatile("cp.async.cg.shared.global [%0], [%1], 16;" :: "r"(dst), "l"(src));
}
#define CPA_COMMIT() asm volatile("cp.async.commit_group;" ::: "memory")
#define CPA_WAIT1()  asm volatile("cp.async.wait_group 1;" ::: "memory")

// ---------------- weight prepass: fp32 -> fp16 ------------------------------
__global__ __launch_bounds__(256) void prepass_w_kernel(
    const float* __restrict__ wk, const float* __restrict__ wv,
    const float* __restrict__ wr, const float* __restrict__ wg,
    const float* __restrict__ wo)
{
    const int p = blockIdx.y;
    const float* W = (p==0)?wk:(p==1)?wv:(p==2)?wr:(p==3)?wg:wo;
    size_t idx = ((size_t)blockIdx.x*256 + threadIdx.x)*4;
    float4 w4 = *(const float4*)(W + idx);
    *(uint2*)(g_W + (size_t)p*SZW + idx) =
        make_uint2(pkh(__float2half(w4.x), __float2half(w4.y)),
                   pkh(__float2half(w4.z), __float2half(w4.w)));
}

// ---------------- activation prepass: mix -> fp16 (RN) ----------------------
__global__ __launch_bounds__(256) void prepass_kernel(
    const float* __restrict__ hidden, const float* __restrict__ mk,
    const float* __restrict__ mv, const float* __restrict__ mr, const float* __restrict__ mg)
{
    int idx = (blockIdx.x*256 + threadIdx.x)*4;
    int t = idx >> 12, c = idx & 4095;
    float4 hv = *(const float4*)(hidden + idx);
    float4 sv = make_float4(0.f,0.f,0.f,0.f);
    if (t > 0) sv = *(const float4*)(hidden + idx - HID);
    const float* ms[4] = {mk, mv, mr, mg};
    #pragma unroll
    for (int p = 0; p < 4; p++){
        float4 m = *(const float4*)(ms[p] + c);
        float x0 = hv.x*m.x + sv.x*(1.f-m.x), x1 = hv.y*m.y + sv.y*(1.f-m.y);
        float x2 = hv.z*m.z + sv.z*(1.f-m.z), x3 = hv.w*m.w + sv.w*(1.f-m.w);
        *(uint2*)(g_mA + (size_t)p*SZ + idx) =
            make_uint2(pkh(__float2half(x0), __float2half(x1)),
                       pkh(__float2half(x2), __float2half(x3)));
    }
}

// ---------------- mma.sync GEMM, 3-stage cp.async, 2 CTAs/SM ----------------
// C[M,N] = A[M,K] * W[N,K]^T.  Tile 128x128, KC=64, 8 warps (4m x 2n).
// Single fp16 term everywhere.  mode 0: proj (z selects); mode 1: out GEMM.
#define KC 64
#define SP 72
#define TH (128*SP)              // elems per tile
#define NSTAGE 3
#define GSMEM (NSTAGE*2*TH*2)    // 110,592 bytes -> 2 CTAs/SM

__global__ __launch_bounds__(256, 2) void gemm_kernel(int mode, float* __restrict__ dout)
{
    extern __shared__ __half sm[];
    const int tid = threadIdx.x, z = blockIdx.z;
    const __half *AG, *BG;
    float* outp;
    bool do_silu = false;
    if (mode == 0){
        AG = g_mA + (size_t)z*SZ;
        BG = g_W + (size_t)z*SZW;
        outp = g_kvrg + (size_t)z*SZ; do_silu = (z==3);
    } else {
        AG = g_ab;
        BG = g_W + 4*(size_t)SZW;
        outp = dout;
    }

    const int m0 = blockIdx.x*128, n0 = blockIdx.y*128;
    const int wid = tid>>5, lane = tid&31;
    const int wm = (wid&3)*32, wn = (wid>>2)*64;
    const int r = lane>>2, q = lane&3;
    const uint32_t sbase = smem_u32(sm);

    const int crow = tid>>3, cseg = tid&7;          // copy: 32 rows x 8 segs / 256 thr
    const size_t gAoff = (size_t)(m0+crow)*HID + cseg*8;
    const size_t gBoff = (size_t)(n0+crow)*HID + cseg*8;
    const uint32_t soff = (uint32_t)(crow*SP + cseg*8)*2;

    float acc[2][8][4];
    #pragma unroll
    for (int i=0;i<2;i++)
        #pragma unroll
        for (int j=0;j<8;j++)
            #pragma unroll
            for (int k=0;k<4;k++) acc[i][j][k]=0.f;

    auto issue = [&](int c, int s){
        const int k0 = c*KC;
        const uint32_t st = sbase + (uint32_t)(s*2*TH)*2;
        #pragma unroll
        for (int i = 0; i < 4; i++){
            const uint32_t dof = soff + (uint32_t)(i*32*SP)*2;
            cpa16(st + dof,                  AG + gAoff + k0 + (size_t)i*32*HID);
            cpa16(st + (uint32_t)TH*2 + dof, BG + gBoff + k0 + (size_t)i*32*HID);
        }
    };

    issue(0, 0); CPA_COMMIT();
    issue(1, 1); CPA_COMMIT();

    const int NCH = HID/KC;
    for (int c = 0; c < NCH; c++){
        const int s = c % NSTAGE;
        CPA_WAIT1();
        __syncthreads();
        if (c + 2 < NCH) issue(c + 2, (c + 2) % NSTAGE);
        CPA_COMMIT();

        const uint32_t stA = sbase + (uint32_t)(s*2*TH)*2;
        const uint32_t stB = stA + (uint32_t)TH*2;

        #pragma unroll
        for (int ko = 0; ko < KC; ko += 16){
            uint32_t aa[2][4], bb[8][2];
            const int arow = wm + (lane&15), acol = ko + (lane>>4)*8;
            #pragma unroll
            for (int fm = 0; fm < 2; fm++){
                const uint32_t ao = (uint32_t)((arow + fm*16)*SP + acol)*2;
                ldsm4(aa[fm], stA + ao);
            }
            const int brow = wn + (lane&7), bcol = ko + ((lane>>3)&1)*8;
            #pragma unroll
            for (int fn = 0; fn < 8; fn++){
                const uint32_t bo = (uint32_t)((brow + fn*8)*SP + bcol)*2;
                ldsm2(bb[fn], stB + bo);
            }
            #pragma unroll
            for (int fn = 0; fn < 8; fn++)
                #pragma unroll
                for (int fm = 0; fm < 2; fm++)
                    mma16816(acc[fm][fn], aa[fm], bb[fn][0], bb[fn][1]);
        }
        __syncthreads();
    }

    #pragma unroll
    for (int fm = 0; fm < 2; fm++){
        #pragma unroll
        for (int fn = 0; fn < 8; fn++){
            int row0 = m0 + wm + fm*16 + r;
            int col  = n0 + wn + fn*8 + q*2;
            float2 v0 = make_float2(acc[fm][fn][0], acc[fm][fn][1]);
            float2 v1 = make_float2(acc[fm][fn][2], acc[fm][fn][3]);
            if (do_silu){
                v0.x = silu(v0.x); v0.y = silu(v0.y);
                v1.x = silu(v1.x); v1.y = silu(v1.y);
            }
            *(float2*)(outp + (size_t)row0*HID + col)     = v0;
            *(float2*)(outp + (size_t)(row0+8)*HID + col) = v1;
        }
    }
}

// ---------------- WKV recurrence, barrier-light -----------------------------
__global__ __launch_bounds__(256) void wkv_kernel(
    const float* __restrict__ time_decay, const float* __restrict__ time_faaaa)
{
    const int head = blockIdx.x, ehalf = blockIdx.y;
    const int tid = threadIdx.x, eg = tid & 31, dg = tid >> 5;
    __shared__ float ks[16][64], rs[16][64], vs[16][32];

    float td[8], tf[8], stv[8];
    #pragma unroll
    for (int j = 0; j < 8; j++){
        int d = dg*8 + j;
        td[j] = expf(-expf(time_decay[head*HD + d]));
        tf[j] = time_faaaa[head*HD + d];
        stv[j] = 0.f;
    }
    const float* kb = g_kvrg + 0*(size_t)SZ + head*HD;
    const float* vb = g_kvrg + 1*(size_t)SZ + head*HD + ehalf*32;
    const float* rb = g_kvrg + 2*(size_t)SZ + head*HD;
    float* op = g_opart + (size_t)dg*SZ + head*HD + ehalf*32;

    const int ktrow = tid >> 4, kseg = tid & 15;
    const int vtrow = tid >> 3, vseg = tid & 7;
    float4 ka, ra, va;
    ka = *(const float4*)(kb + (size_t)ktrow*HID + kseg*4);
    ra = *(const float4*)(rb + (size_t)ktrow*HID + kseg*4);
    if (tid < 128) va = *(const float4*)(vb + (size_t)vtrow*HID + vseg*4);

    for (int c = 0; c < SEQ/16; c++){
        __syncthreads();
        *(float4*)&ks[ktrow][kseg*4] = ka;
        *(float4*)&rs[ktrow][kseg*4] = ra;
        if (tid < 128) *(float4*)&vs[vtrow][vseg*4] = va;
        __syncthreads();
        if (c < SEQ/16 - 1){
            const size_t t1 = (size_t)(c+1)*16;
            ka = *(const float4*)(kb + (t1+ktrow)*HID + kseg*4);
            ra = *(const float4*)(rb + (t1+ktrow)*HID + kseg*4);
            if (tid < 128) va = *(const float4*)(vb + (t1+vtrow)*HID + vseg*4);
        }
        #pragma unroll
        for (int tt = 0; tt < 16; tt++){
            const float ve = vs[tt][eg];
            float4 k0 = *(const float4*)&ks[tt][dg*8];
            float4 k1 = *(const float4*)&ks[tt][dg*8+4];
            float4 r0 = *(const float4*)&rs[tt][dg*8];
            float4 r1 = *(const float4*)&rs[tt][dg*8+4];
            float kv, o = 0.f;
            kv = k0.x*ve; o = fmaf(r0.x, fmaf(tf[0],kv,stv[0]), o); stv[0] = fmaf(td[0],stv[0],kv);
            kv = k0.y*ve; o = fmaf(r0.y, fmaf(tf[1],kv,stv[1]), o); stv[1] = fmaf(td[1],stv[1],kv);
            kv = k0.z*ve; o = fmaf(r0.z, fmaf(tf[2],kv,stv[2]), o); stv[2] = fmaf(td[2],stv[2],kv);
            kv = k0.w*ve; o = fmaf(r0.w, fmaf(tf[3],kv,stv[3]), o); stv[3] = fmaf(td[3],stv[3],kv);
            kv = k1.x*ve; o = fmaf(r1.x, fmaf(tf[4],kv,stv[4]), o); stv[4] = fmaf(td[4],stv[4],kv);
            kv = k1.y*ve; o = fmaf(r1.y, fmaf(tf[5],kv,stv[5]), o); stv[5] = fmaf(td[5],stv[5],kv);
            kv = k1.z*ve; o = fmaf(r1.z, fmaf(tf[6],kv,stv[6]), o); stv[6] = fmaf(td[6],stv[6],kv);
            kv = k1.w*ve; o = fmaf(r1.w, fmaf(tf[7],kv,stv[7]), o); stv[7] = fmaf(td[7],stv[7],kv);
            op[(size_t)(c*16+tt)*HID + eg] = o;
        }
    }
}

// ---------------- GroupNorm + gate -> fp16 ----------------------------------
__global__ __launch_bounds__(256) void norm_kernel(
    const float* __restrict__ gnw, const float* __restrict__ gnb)
{
    const int wid = threadIdx.x >> 5, lane = threadIdx.x & 31;
    const int g = blockIdx.x*8 + wid;
    const int t = g >> 6, h = g & 63, e0 = lane*2;
    const size_t bse = (size_t)t*HID + h*HD + e0;

    float o0 = 0.f, o1 = 0.f;
    #pragma unroll
    for (int dg = 0; dg < 8; dg++){
        float2 v = *(const float2*)(g_opart + (size_t)dg*SZ + bse);
        o0 += v.x; o1 += v.y;
    }
    float s = o0 + o1, s2 = o0*o0 + o1*o1;
    #pragma unroll
    for (int off = 16; off > 0; off >>= 1){
        s  += __shfl_xor_sync(0xffffffffu, s,  off);
        s2 += __shfl_xor_sync(0xffffffffu, s2, off);
    }
    const float mean = s * (1.f/64.f);
    const float var  = s2 * (1.f/64.f) - mean*mean;
    const float rstd = rsqrtf(var + 1e-5f);
    float2 gt = *(const float2*)(g_kvrg + 3*(size_t)SZ + bse);
    const float w0 = gnw[h*HD+e0], w1 = gnw[h*HD+e0+1];
    const float b0 = gnb[h*HD+e0], b1 = gnb[h*HD+e0+1];
    float y0 = ((o0-mean)*rstd*w0 + b0) * gt.x;
    float y1 = ((o1-mean)*rstd*w1 + b1) * gt.y;
    *(uint32_t*)(g_ab + bse) = pkh(__float2half(y0), __float2half(y1));
}

// ---------------------------------------------------------------------------
extern "C" void kernel_launch(void* const* d_in, const int* in_sizes, int n_in,
                              void* d_out, int out_size)
{
    const float* hidden     = (const float*)d_in[0];
    const float* w_key      = (const float*)d_in[1];
    const float* w_value    = (const float*)d_in[2];
    const float* w_recept   = (const float*)d_in[3];
    const float* w_gate     = (const float*)d_in[4];
    const float* w_output   = (const float*)d_in[5];
    const float* tm_key     = (const float*)d_in[6];
    const float* tm_value   = (const float*)d_in[7];
    const float* tm_recept  = (const float*)d_in[8];
    const float* tm_gate    = (const float*)d_in[9];
    const float* time_decay = (const float*)d_in[10];
    const float* time_faaaa = (const float*)d_in[11];
    const float* gn_w       = (const float*)d_in[12];
    const float* gn_b       = (const float*)d_in[13];

    cudaFuncSetAttribute(gemm_kernel, cudaFuncAttributeMaxDynamicSharedMemorySize, GSMEM);

    dim3 gw(SZW/1024, 5);
    prepass_w_kernel<<<gw, 256>>>(w_key, w_value, w_recept, w_gate, w_output);
    prepass_kernel<<<SZ/1024, 256>>>(hidden, tm_key, tm_value, tm_recept, tm_gate);

    dim3 gproj(SEQ/128, HID/128, 4);
    gemm_kernel<<<gproj, 256, GSMEM>>>(0, nullptr);

    dim3 gwkv(NH, 2);
    wkv_kernel<<<gwkv, 256>>>(time_decay, time_faaaa);

    norm_kernel<<<SEQ*NH/8, 256>>>(gn_w, gn_b);

    dim3 gout(SEQ/128, HID/128, 1);
    gemm_kernel<<<gout, 256, GSMEM>>>(1, (float*)d_out);
}

// round 12
// speedup vs baseline: 2.5560x; 1.0006x over previous
#include <cuda_runtime.h>
#include <cuda_fp16.h>
#include <math.h>
#include <stdint.h>

#define SEQ 1024
#define HID 4096
#define NH  64
#define HD  64
#define SZ  (SEQ*HID)
#define SZW (HID*HID)

__device__ float   g_kvrg[4*SZ];     // k,v,r,g fp32
__device__ float   g_osum[SZ];       // WKV output (dgroup-reduced) fp32
__device__ __half  g_mA[4*SZ];       // mixed activations fp16 (RN)
__device__ __half  g_ab[SZ];         // normed/gated fp16
__device__ __half  g_W[5*SZW];       // weights fp16 (k,v,r,g,o)

__device__ __forceinline__ uint32_t pkh(__half a, __half b){
    __half2 t = __halves2half2(a, b);
    return *reinterpret_cast<uint32_t*>(&t);
}
__device__ __forceinline__ float silu(float x){ return x / (1.f + expf(-x)); }
__device__ __forceinline__ uint32_t smem_u32(const void* p){
    uint32_t a;
    asm("{ .reg .u64 t; cvta.to.shared.u64 t, %1; cvt.u32.u64 %0, t; }" : "=r"(a) : "l"(p));
    return a;
}
__device__ __forceinline__ void mma16816(float* c, const uint32_t* a, uint32_t b0, uint32_t b1){
    asm volatile("mma.sync.aligned.m16n8k16.row.col.f32.f16.f16.f32 "
        "{%0,%1,%2,%3}, {%4,%5,%6,%7}, {%8,%9}, {%0,%1,%2,%3};"
        : "+f"(c[0]), "+f"(c[1]), "+f"(c[2]), "+f"(c[3])
        : "r"(a[0]), "r"(a[1]), "r"(a[2]), "r"(a[3]), "r"(b0), "r"(b1));
}
__device__ __forceinline__ void ldsm4(uint32_t* r, uint32_t a){
    asm volatile("ldmatrix.sync.aligned.m8n8.x4.shared.b16 {%0,%1,%2,%3}, [%4];"
        : "=r"(r[0]), "=r"(r[1]), "=r"(r[2]), "=r"(r[3]) : "r"(a));
}
__device__ __forceinline__ void ldsm2(uint32_t* r, uint32_t a){
    asm volatile("ldmatrix.sync.aligned.m8n8.x2.shared.b16 {%0,%1}, [%2];"
        : "=r"(r[0]), "=r"(r[1]) : "r"(a));
}
__device__ __forceinline__ void cpa16(uint32_t dst, const void* src){
    asm volatile("cp.async.cg.shared.global [%0], [%1], 16;" :: "r"(dst), "l"(src));
}
#define CPA_COMMIT() asm volatile("cp.async.commit_group;" ::: "memory")
#define CPA_WAIT1()  asm volatile("cp.async.wait_group 1;" ::: "memory")

// ---------------- weight prepass: fp32 -> fp16 ------------------------------
__global__ __launch_bounds__(256) void prepass_w_kernel(
    const float* __restrict__ wk, const float* __restrict__ wv,
    const float* __restrict__ wr, const float* __restrict__ wg,
    const float* __restrict__ wo)
{
    const int p = blockIdx.y;
    const float* W = (p==0)?wk:(p==1)?wv:(p==2)?wr:(p==3)?wg:wo;
    size_t idx = ((size_t)blockIdx.x*256 + threadIdx.x)*4;
    float4 w4 = *(const float4*)(W + idx);
    *(uint2*)(g_W + (size_t)p*SZW + idx) =
        make_uint2(pkh(__float2half(w4.x), __float2half(w4.y)),
                   pkh(__float2half(w4.z), __float2half(w4.w)));
}

// ---------------- activation prepass: mix -> fp16 (RN) ----------------------
__global__ __launch_bounds__(256) void prepass_kernel(
    const float* __restrict__ hidden, const float* __restrict__ mk,
    const float* __restrict__ mv, const float* __restrict__ mr, const float* __restrict__ mg)
{
    int idx = (blockIdx.x*256 + threadIdx.x)*4;
    int t = idx >> 12, c = idx & 4095;
    float4 hv = *(const float4*)(hidden + idx);
    float4 sv = make_float4(0.f,0.f,0.f,0.f);
    if (t > 0) sv = *(const float4*)(hidden + idx - HID);
    const float* ms[4] = {mk, mv, mr, mg};
    #pragma unroll
    for (int p = 0; p < 4; p++){
        float4 m = *(const float4*)(ms[p] + c);
        float x0 = hv.x*m.x + sv.x*(1.f-m.x), x1 = hv.y*m.y + sv.y*(1.f-m.y);
        float x2 = hv.z*m.z + sv.z*(1.f-m.z), x3 = hv.w*m.w + sv.w*(1.f-m.w);
        *(uint2*)(g_mA + (size_t)p*SZ + idx) =
            make_uint2(pkh(__float2half(x0), __float2half(x1)),
                       pkh(__float2half(x2), __float2half(x3)));
    }
}

// ---------------- mma.sync GEMM, 3-stage cp.async, 2 CTAs/SM ----------------
#define KC 64
#define SP 72
#define TH (128*SP)
#define NSTAGE 3
#define GSMEM (NSTAGE*2*TH*2)

__global__ __launch_bounds__(256, 2) void gemm_kernel(int mode, float* __restrict__ dout)
{
    extern __shared__ __half sm[];
    const int tid = threadIdx.x, z = blockIdx.z;
    const __half *AG, *BG;
    float* outp;
    bool do_silu = false;
    if (mode == 0){
        AG = g_mA + (size_t)z*SZ;
        BG = g_W + (size_t)z*SZW;
        outp = g_kvrg + (size_t)z*SZ; do_silu = (z==3);
    } else {
        AG = g_ab;
        BG = g_W + 4*(size_t)SZW;
        outp = dout;
    }

    const int m0 = blockIdx.x*128, n0 = blockIdx.y*128;
    const int wid = tid>>5, lane = tid&31;
    const int wm = (wid&3)*32, wn = (wid>>2)*64;
    const int r = lane>>2, q = lane&3;
    const uint32_t sbase = smem_u32(sm);

    const int crow = tid>>3, cseg = tid&7;
    const size_t gAoff = (size_t)(m0+crow)*HID + cseg*8;
    const size_t gBoff = (size_t)(n0+crow)*HID + cseg*8;
    const uint32_t soff = (uint32_t)(crow*SP + cseg*8)*2;

    float acc[2][8][4];
    #pragma unroll
    for (int i=0;i<2;i++)
        #pragma unroll
        for (int j=0;j<8;j++)
            #pragma unroll
            for (int k=0;k<4;k++) acc[i][j][k]=0.f;

    auto issue = [&](int c, int s){
        const int k0 = c*KC;
        const uint32_t st = sbase + (uint32_t)(s*2*TH)*2;
        #pragma unroll
        for (int i = 0; i < 4; i++){
            const uint32_t dof = soff + (uint32_t)(i*32*SP)*2;
            cpa16(st + dof,                  AG + gAoff + k0 + (size_t)i*32*HID);
            cpa16(st + (uint32_t)TH*2 + dof, BG + gBoff + k0 + (size_t)i*32*HID);
        }
    };

    issue(0, 0); CPA_COMMIT();
    issue(1, 1); CPA_COMMIT();

    const int NCH = HID/KC;
    for (int c = 0; c < NCH; c++){
        const int s = c % NSTAGE;
        CPA_WAIT1();
        __syncthreads();
        if (c + 2 < NCH) issue(c + 2, (c + 2) % NSTAGE);
        CPA_COMMIT();

        const uint32_t stA = sbase + (uint32_t)(s*2*TH)*2;
        const uint32_t stB = stA + (uint32_t)TH*2;

        #pragma unroll
        for (int ko = 0; ko < KC; ko += 16){
            uint32_t aa[2][4], bb[8][2];
            const int arow = wm + (lane&15), acol = ko + (lane>>4)*8;
            #pragma unroll
            for (int fm = 0; fm < 2; fm++){
                const uint32_t ao = (uint32_t)((arow + fm*16)*SP + acol)*2;
                ldsm4(aa[fm], stA + ao);
            }
            const int brow = wn + (lane&7), bcol = ko + ((lane>>3)&1)*8;
            #pragma unroll
            for (int fn = 0; fn < 8; fn++){
                const uint32_t bo = (uint32_t)((brow + fn*8)*SP + bcol)*2;
                ldsm2(bb[fn], stB + bo);
            }
            #pragma unroll
            for (int fn = 0; fn < 8; fn++)
                #pragma unroll
                for (int fm = 0; fm < 2; fm++)
                    mma16816(acc[fm][fn], aa[fm], bb[fn][0], bb[fn][1]);
        }
        __syncthreads();
    }

    #pragma unroll
    for (int fm = 0; fm < 2; fm++){
        #pragma unroll
        for (int fn = 0; fn < 8; fn++){
            int row0 = m0 + wm + fm*16 + r;
            int col  = n0 + wn + fn*8 + q*2;
            float2 v0 = make_float2(acc[fm][fn][0], acc[fm][fn][1]);
            float2 v1 = make_float2(acc[fm][fn][2], acc[fm][fn][3]);
            if (do_silu){
                v0.x = silu(v0.x); v0.y = silu(v0.y);
                v1.x = silu(v1.x); v1.y = silu(v1.y);
            }
            *(float2*)(outp + (size_t)row0*HID + col)     = v0;
            *(float2*)(outp + (size_t)(row0+8)*HID + col) = v1;
        }
    }
}

// ---------------- WKV recurrence: 512 thr, in-smem dgroup reduction ---------
// grid (NH, 2): head x e-half.  16 dgroups x 32 e; 4 d-states per thread.
__global__ __launch_bounds__(512) void wkv_kernel(
    const float* __restrict__ time_decay, const float* __restrict__ time_faaaa)
{
    const int head = blockIdx.x, ehalf = blockIdx.y;
    const int tid = threadIdx.x, eg = tid & 31, dg = tid >> 5;   // dg 0..15
    __shared__ float ks[16][64], rs[16][64], vs[16][32];
    __shared__ float sop[16][16][33];                            // [dg][tt][eg], padded

    float td[4], tf[4], st[4];
    #pragma unroll
    for (int j = 0; j < 4; j++){
        int d = dg*4 + j;
        td[j] = expf(-expf(time_decay[head*HD + d]));
        tf[j] = time_faaaa[head*HD + d];
        st[j] = 0.f;
    }
    const float* kb = g_kvrg + 0*(size_t)SZ + head*HD;
    const float* vb = g_kvrg + 1*(size_t)SZ + head*HD + ehalf*32;
    const float* rb = g_kvrg + 2*(size_t)SZ + head*HD;
    float* op = g_osum + head*HD + ehalf*32;

    // staging loaders: tid<256 -> k (16 rows x 16 float4), tid>=256 -> r; tid<128 -> v
    const int krow = (tid & 255) >> 4, kseg = tid & 15;
    const int vrow = tid >> 3, vseg = tid & 7;
    float4 kra, va;
    if (tid < 256) kra = *(const float4*)(kb + (size_t)krow*HID + kseg*4);
    else           kra = *(const float4*)(rb + (size_t)krow*HID + kseg*4);
    if (tid < 128) va  = *(const float4*)(vb + (size_t)vrow*HID + vseg*4);

    const int rtt = tid >> 5;          // reduce: tt index (0..15)
    for (int c = 0; c < SEQ/16; c++){
        if (tid < 256) *(float4*)&ks[krow][kseg*4] = kra;
        else           *(float4*)&rs[krow][kseg*4] = kra;
        if (tid < 128) *(float4*)&vs[vrow][vseg*4] = va;
        __syncthreads();                                  // bar_A: staging/sop ready
        if (c < SEQ/16 - 1){
            const size_t t1 = (size_t)(c+1)*16;
            if (tid < 256) kra = *(const float4*)(kb + (t1+krow)*HID + kseg*4);
            else           kra = *(const float4*)(rb + (t1+krow)*HID + kseg*4);
            if (tid < 128) va  = *(const float4*)(vb + (t1+vrow)*HID + vseg*4);
        }
        #pragma unroll
        for (int tt = 0; tt < 16; tt++){
            const float ve = vs[tt][eg];
            float4 k4 = *(const float4*)&ks[tt][dg*4];
            float4 r4 = *(const float4*)&rs[tt][dg*4];
            float kv, o0, o1;
            kv = k4.x*ve; o0 = r4.x * fmaf(tf[0],kv,st[0]); st[0] = fmaf(td[0],st[0],kv);
            kv = k4.y*ve; o1 = r4.y * fmaf(tf[1],kv,st[1]); st[1] = fmaf(td[1],st[1],kv);
            kv = k4.z*ve; o0 = fmaf(r4.z, fmaf(tf[2],kv,st[2]), o0); st[2] = fmaf(td[2],st[2],kv);
            kv = k4.w*ve; o1 = fmaf(r4.w, fmaf(tf[3],kv,st[3]), o1); st[3] = fmaf(td[3],st[3],kv);
            sop[dg][tt][eg] = o0 + o1;
        }
        __syncthreads();                                  // bar_B: sop complete
        float s = 0.f;
        #pragma unroll
        for (int d2 = 0; d2 < 16; d2++) s += sop[d2][rtt][eg];
        op[(size_t)(c*16 + rtt)*HID + eg] = s;
        __syncthreads();                                  // reduce done before re-stage
    }
}

// ---------------- GroupNorm + gate -> fp16 ----------------------------------
__global__ __launch_bounds__(256) void norm_kernel(
    const float* __restrict__ gnw, const float* __restrict__ gnb)
{
    const int wid = threadIdx.x >> 5, lane = threadIdx.x & 31;
    const int g = blockIdx.x*8 + wid;
    const int t = g >> 6, h = g & 63, e0 = lane*2;
    const size_t bse = (size_t)t*HID + h*HD + e0;

    float2 ov = *(const float2*)(g_osum + bse);
    float o0 = ov.x, o1 = ov.y;
    float s = o0 + o1, s2 = o0*o0 + o1*o1;
    #pragma unroll
    for (int off = 16; off > 0; off >>= 1){
        s  += __shfl_xor_sync(0xffffffffu, s,  off);
        s2 += __shfl_xor_sync(0xffffffffu, s2, off);
    }
    const float mean = s * (1.f/64.f);
    const float var  = s2 * (1.f/64.f) - mean*mean;
    const float rstd = rsqrtf(var + 1e-5f);
    float2 gt = *(const float2*)(g_kvrg + 3*(size_t)SZ + bse);
    const float w0 = gnw[h*HD+e0], w1 = gnw[h*HD+e0+1];
    const float b0 = gnb[h*HD+e0], b1 = gnb[h*HD+e0+1];
    float y0 = ((o0-mean)*rstd*w0 + b0) * gt.x;
    float y1 = ((o1-mean)*rstd*w1 + b1) * gt.y;
    *(uint32_t*)(g_ab + bse) = pkh(__float2half(y0), __float2half(y1));
}

// ---------------------------------------------------------------------------
extern "C" void kernel_launch(void* const* d_in, const int* in_sizes, int n_in,
                              void* d_out, int out_size)
{
    const float* hidden     = (const float*)d_in[0];
    const float* w_key      = (const float*)d_in[1];
    const float* w_value    = (const float*)d_in[2];
    const float* w_recept   = (const float*)d_in[3];
    const float* w_gate     = (const float*)d_in[4];
    const float* w_output   = (const float*)d_in[5];
    const float* tm_key     = (const float*)d_in[6];
    const float* tm_value   = (const float*)d_in[7];
    const float* tm_recept  = (const float*)d_in[8];
    const float* tm_gate    = (const float*)d_in[9];
    const float* time_decay = (const float*)d_in[10];
    const float* time_faaaa = (const float*)d_in[11];
    const float* gn_w       = (const float*)d_in[12];
    const float* gn_b       = (const float*)d_in[13];

    cudaFuncSetAttribute(gemm_kernel, cudaFuncAttributeMaxDynamicSharedMemorySize, GSMEM);

    dim3 gw(SZW/1024, 5);
    prepass_w_kernel<<<gw, 256>>>(w_key, w_value, w_recept, w_gate, w_output);
    prepass_kernel<<<SZ/1024, 256>>>(hidden, tm_key, tm_value, tm_recept, tm_gate);

    dim3 gproj(SEQ/128, HID/128, 4);
    gemm_kernel<<<gproj, 256, GSMEM>>>(0, nullptr);

    dim3 gwkv(NH, 2);
    wkv_kernel<<<gwkv, 512>>>(time_decay, time_faaaa);

    norm_kernel<<<SEQ*NH/8, 256>>>(gn_w, gn_b);

    dim3 gout(SEQ/128, HID/128, 1);
    gemm_kernel<<<gout, 256, GSMEM>>>(1, (float*)d_out);
}